// round 12
// baseline (speedup 1.0000x reference)
#include <cuda_runtime.h>
#include <cuda_fp16.h>
#include <cstdint>

#define NB 64
#define NT 512          // 16 compute warps: 8 m-positions x 2 n-halves
#define BB 128
#define TT 1024
#define FF 64
#define HH 512

typedef unsigned long long ull;

// ---------------- device scratch ----------------
__device__ __align__(1024) unsigned char g_hh[2][8 * 16384];     // h fp16 chunk tiles
__device__ __align__(1024) unsigned char g_xh[(size_t)TT * 16384]; // x fp16 tiles
__device__ float g_hist[(size_t)TT * HH * BB];   // decoder-input h [kd][j][b]
__device__ float g_woutT[HH * FF];
__device__ unsigned int g_flag[8];
__device__ unsigned int g_count = 0, g_gen = 0;

// ---------------- smem byte offsets ----------------
#define OFF_WBE  0          // enc B frags: 9 ch * 8192  ([bh0,bh1,bl0,bl1] 16B/lane)
#define OFF_WBD  73728      // dec B frags: 8 ch * 8192
#define OFF_A    139264     // 3 stages * 16384
#define OFF_BE   188416     // 32 floats
#define OFF_BD   188544     // 32 floats
#define SMEM_BYTES 188672

static __device__ __forceinline__ uint32_t sw128(uint32_t o) {
    return o ^ ((o >> 3) & 0x70);
}
__device__ __forceinline__ float sigf(float x) {
    return __fdividef(1.0f, 1.0f + __expf(-x));
}
__device__ __forceinline__ float tanhfast(float x) {
    return 1.0f - __fdividef(2.0f, __expf(2.0f * x) + 1.0f);
}

__device__ __forceinline__ void grid_barrier_init() {
    __syncthreads();
    if (threadIdx.x == 0) {
        unsigned int cur0;
        asm volatile("ld.acquire.gpu.b32 %0, [%1];" : "=r"(cur0) : "l"(&g_gen) : "memory");
        unsigned int target = cur0 + 1u;
        __threadfence();
        unsigned int t = atomicAdd(&g_count, 1u);
        if (t == NB - 1u) {
            g_count = 0u;
            asm volatile("st.release.gpu.b32 [%0], %1;" :: "l"(&g_gen), "r"(target) : "memory");
        } else {
            unsigned int cur;
            do {
                __nanosleep(20);
                asm volatile("ld.acquire.gpu.b32 %0, [%1];" : "=r"(cur) : "l"(&g_gen) : "memory");
            } while ((int)(cur - target) < 0);
        }
    }
    __syncthreads();
}
__device__ __forceinline__ void wait_flag(int ch, unsigned int tgt) {
    unsigned int v;
    asm volatile("ld.acquire.gpu.b32 %0, [%1];" : "=r"(v) : "l"(&g_flag[ch]) : "memory");
    while ((int)(v - tgt) < 0) {
        __nanosleep(32);
        asm volatile("ld.acquire.gpu.b32 %0, [%1];" : "=r"(v) : "l"(&g_flag[ch]) : "memory");
    }
}

// stage one 16KB fp16 chunk: 2 cp.async.cg per thread (512 threads)
__device__ __forceinline__ void prefetch_chunk(uint32_t dst, const unsigned char* src, int tid) {
#pragma unroll
    for (int i = 0; i < 2; i++) {
        uint32_t off = (uint32_t)(tid + NT * i) * 16u;
        asm volatile("cp.async.cg.shared.global [%0], [%1], 16;"
                     :: "r"(dst + off), "l"(src + off) : "memory");
    }
    asm volatile("cp.async.commit_group;" ::: "memory");
}

__device__ __forceinline__ void ldmx4(uint32_t addr, uint32_t* a) {
    asm volatile("ldmatrix.sync.aligned.m8n8.x4.shared.b16 {%0,%1,%2,%3}, [%4];"
                 : "=r"(a[0]), "=r"(a[1]), "=r"(a[2]), "=r"(a[3]) : "r"(addr));
}
__device__ __forceinline__ void mma16816(float* d, const uint32_t* a, uint32_t b0, uint32_t b1) {
    asm volatile(
        "mma.sync.aligned.m16n8k16.row.col.f32.f16.f16.f32 "
        "{%0,%1,%2,%3}, {%4,%5,%6,%7}, {%8,%9}, {%0,%1,%2,%3};"
        : "+f"(d[0]), "+f"(d[1]), "+f"(d[2]), "+f"(d[3])
        : "r"(a[0]), "r"(a[1]), "r"(a[2]), "r"(a[3]), "r"(b0), "r"(b1));
}
__device__ __forceinline__ uint32_t pack_h2(float lo, float hi) {
    uint32_t r;
    asm("cvt.rn.f16x2.f32 %0, %1, %2;" : "=r"(r) : "f"(hi), "f"(lo));
    return r;
}

// consume one staged chunk (warp's n-half): 4 ldmatrix + 8 LDS.128 + 16 HMMA
__device__ __forceinline__ void consume_chunk(uint32_t sa, uint32_t wb,
                                              uint32_t abase, int lane, int nh,
                                              float* D0, float* D1) {
#pragma unroll
    for (int ks = 0; ks < 4; ++ks) {
        uint32_t ao = sw128(abase + (uint32_t)ks * 32u);
        uint32_t a[4];
        ldmx4(sa + ao, a);
#pragma unroll
        for (int ntl = 0; ntl < 2; ++ntl) {
            uint32_t fb = wb + (uint32_t)(ks * 4 + nh * 2 + ntl) * 512u + (uint32_t)lane * 16u;
            uint32_t bh0, bh1, bl0, bl1;
            asm("ld.shared.v4.b32 {%0,%1,%2,%3}, [%4];"
                : "=r"(bh0), "=r"(bh1), "=r"(bl0), "=r"(bl1) : "r"(fb));
            float* D = ntl ? D1 : D0;
            mma16816(D, a, bh0, bh1);
            mma16816(D, a, bl0, bl1);
        }
    }
}

__global__ void reset_flags_kernel() {
    if (threadIdx.x < 8) g_flag[threadIdx.x] = 8u;   // h_0 ready baseline (8 CTAs/chunk)
}

__global__ void __launch_bounds__(NT, 1) lstm_persistent(
    const float* __restrict__ ts,
    const float* __restrict__ w_ih_enc, const float* __restrict__ w_hh_enc,
    const float* __restrict__ b_ih_enc, const float* __restrict__ b_hh_enc,
    const float* __restrict__ w_ih_dec, const float* __restrict__ w_hh_dec,
    const float* __restrict__ b_ih_dec, const float* __restrict__ b_hh_dec,
    const float* __restrict__ w_out, const float* __restrict__ b_out,
    float* __restrict__ out)
{
    extern __shared__ unsigned char smem[];
    const int tid = threadIdx.x;
    const int cid = blockIdx.x;
    const int jb = cid * 8;           // first hidden col owned (8 per CTA)
    const int gidx = cid >> 3;        // chunk this CTA's h columns belong to
    const uint32_t sb = (uint32_t)__cvta_generic_to_shared(smem);

    // ======== INIT: encoder B fragments, fp16 hi + residual lo ========
    // e -> (ch 0..8, ks 0..3, nt 0..3, lane 0..31) ; n = nt*8+gid in 0..31
    for (int e = tid; e < 9 * 16 * 32; e += NT) {
        int lane = e & 31, rem = e >> 5;
        int nt = rem & 3, ks = (rem >> 2) & 3, ch = rem >> 4;
        int gid = lane >> 2, tig = lane & 3;
        int n = nt * 8 + gid, jl = n >> 2, q = n & 3;
        int row = q * HH + jb + jl;
        float v[4];
#pragma unroll
        for (int d = 0; d < 4; ++d) {
            int kin = ks * 16 + 2 * tig + ((d & 2) ? 8 : 0) + (d & 1);
            v[d] = (ch < 8) ? w_hh_enc[(size_t)row * HH + ch * 64 + kin]
                            : w_ih_enc[(size_t)row * FF + kin];
        }
        float hi[4], lo[4];
#pragma unroll
        for (int d = 0; d < 4; ++d) {
            hi[d] = __half2float(__float2half_rn(v[d]));
            lo[d] = v[d] - hi[d];
        }
        uint32_t base = (uint32_t)(ch * 16 + ks * 4 + nt) * 512u + (uint32_t)lane * 16u;
        uint32_t* p = (uint32_t*)(smem + OFF_WBE + base);
        p[0] = pack_h2(hi[0], hi[1]); p[1] = pack_h2(hi[2], hi[3]);
        p[2] = pack_h2(lo[0], lo[1]); p[3] = pack_h2(lo[2], lo[3]);
    }
    // ======== INIT: decoder fused B fragments (W_eff = w_hh + w_ih @ w_out) ========
    for (int e = tid; e < 8 * 16 * 32; e += NT) {
        int lane = e & 31, rem = e >> 5;
        int nt = rem & 3, ks = (rem >> 2) & 3, ch = rem >> 4;
        int gid = lane >> 2, tig = lane & 3;
        int n = nt * 8 + gid, jl = n >> 2, q = n & 3;
        int row = q * HH + jb + jl;
        const float* wr = w_ih_dec + (size_t)row * FF;
        float v[4];
#pragma unroll
        for (int d = 0; d < 4; ++d) {
            int k = ch * 64 + ks * 16 + 2 * tig + ((d & 2) ? 8 : 0) + (d & 1);
            float acc = w_hh_dec[(size_t)row * HH + k];
#pragma unroll 8
            for (int f = 0; f < FF; ++f) acc += wr[f] * w_out[(size_t)f * HH + k];
            v[d] = acc;
        }
        float hi[4], lo[4];
#pragma unroll
        for (int d = 0; d < 4; ++d) {
            hi[d] = __half2float(__float2half_rn(v[d]));
            lo[d] = v[d] - hi[d];
        }
        uint32_t base = (uint32_t)(ch * 16 + ks * 4 + nt) * 512u + (uint32_t)lane * 16u;
        uint32_t* p = (uint32_t*)(smem + OFF_WBD + base);
        p[0] = pack_h2(hi[0], hi[1]); p[1] = pack_h2(hi[2], hi[3]);
        p[2] = pack_h2(lo[0], lo[1]); p[3] = pack_h2(lo[2], lo[3]);
    }
    // biases [jl 0..7][q 0..3]
    if (tid < 32) {
        int jl = tid >> 2, q = tid & 3;
        int row = q * HH + jb + jl;
        ((float*)(smem + OFF_BE))[jl * 4 + q] = b_ih_enc[row] + b_hh_enc[row];
        float v = b_ih_dec[row] + b_hh_dec[row];
        const float* wr = w_ih_dec + (size_t)row * FF;
#pragma unroll 8
        for (int f = 0; f < FF; ++f) v += wr[f] * b_out[f];
        ((float*)(smem + OFF_BD))[jl * 4 + q] = v;
    }
    // x tiles: [t][b*128B] fp16, swizzled; 16 t per CTA
    for (int tt = 0; tt < TT / NB; ++tt) {
        int t = cid * (TT / NB) + tt;
        for (int idx = tid; idx < BB * 16; idx += NT) {
            int b = idx >> 4, f4 = (idx & 15) * 4;
            float v0 = ts[((size_t)b * TT + t) * FF + f4];
            float v1 = ts[((size_t)b * TT + t) * FF + f4 + 1];
            float v2 = ts[((size_t)b * TT + t) * FF + f4 + 2];
            float v3 = ts[((size_t)b * TT + t) * FF + f4 + 3];
            uint32_t o = sw128((uint32_t)(b * 128 + f4 * 2));
            *(uint2*)(g_xh + (size_t)t * 16384 + o) =
                make_uint2(pack_h2(v0, v1), pack_h2(v2, v3));
        }
    }
    // zero own h_0 slice (8 cols x 128 b)
    if (tid < 128) {
        uint32_t o = sw128((uint32_t)(tid * 128 + (cid & 7) * 16));
        *(uint4*)(g_hh[0] + (size_t)gidx * 16384 + o) = make_uint4(0, 0, 0, 0);
    }
    if (cid == 0) {
        for (int idx = tid; idx < HH * FF; idx += NT) {
            int j = idx >> 6, f = idx & 63;
            g_woutT[j * FF + f] = w_out[(size_t)f * HH + j];
        }
    }
    grid_barrier_init();

    // ======== persistent recurrence ========
    const int wid = tid >> 5, lane = tid & 31;
    const int mw = wid & 7, nh = wid >> 3;      // m-position, n-half
    const int gid = lane >> 2, tig = lane & 3;
    const uint32_t abase = (uint32_t)(((mw << 4) + (lane & 15)) * 128 + ((lane >> 4) & 1) * 16);

    float c0s = 0.0f, c8s = 0.0f;

    for (int s = 0; s < 2 * TT; ++s) {
        const bool enc = (s < TT);
        const int nc = enc ? 9 : 8;
        if (s == TT) { c0s = 0.0f; c8s = 0.0f; }
        const unsigned int tgt = 8u * (unsigned)(s + 1);

        if (tid < 8) wait_flag(tid, tgt);    // parallel upfront wait
        __syncthreads();

        const unsigned char* hh = g_hh[s & 1];
#define SRC(i) (enc ? ((i) == 0 ? g_xh + (size_t)s * 16384 : hh + (size_t)((i) - 1) * 16384) \
                    : hh + (size_t)(i) * 16384)

        prefetch_chunk(sb + OFF_A, SRC(0), tid);
        prefetch_chunk(sb + OFF_A + 16384u, SRC(1), tid);

        float D0[4] = {0, 0, 0, 0}, D1[4] = {0, 0, 0, 0};

        for (int i = 0; i < nc; ++i) {
            if (i + 1 < nc) {
                asm volatile("cp.async.wait_group 1;" ::: "memory");
            } else {
                asm volatile("cp.async.wait_group 0;" ::: "memory");
            }
            __syncthreads();   // chunk i landed; stage (i+2)%3 free
            if (i + 2 < nc) {
                prefetch_chunk(sb + OFF_A + (uint32_t)((i + 2) % 3) * 16384u, SRC(i + 2), tid);
            }
            int ch = enc ? (i == 0 ? 8 : i - 1) : i;
            uint32_t wb = sb + (enc ? OFF_WBE : OFF_WBD) + (uint32_t)ch * 8192u;
            consume_chunk(sb + OFF_A + (uint32_t)(i % 3) * 16384u, wb, abase, lane, nh, D0, D1);
        }
#undef SRC

        // ---- epilogue: gate pairing via shfl, cell update ----
        bool ev = ((tig & 1) == 0);
        float s0 = ev ? D1[0] : D0[0];
        float s1 = ev ? D1[1] : D0[1];
        float s2 = ev ? D1[2] : D0[2];
        float s3 = ev ? D1[3] : D0[3];
        float r0 = __shfl_xor_sync(0xffffffffu, s0, 1);
        float r1 = __shfl_xor_sync(0xffffffffu, s1, 1);
        float r2 = __shfl_xor_sync(0xffffffffu, s2, 1);
        float r3 = __shfl_xor_sync(0xffffffffu, s3, 1);
        float gi0, gf0, gi8, gf8, gg0, go0, gg8, go8;
        int jl;
        if (ev) {
            gi0 = D0[0]; gf0 = D0[1]; gi8 = D0[2]; gf8 = D0[3];
            gg0 = r0; go0 = r1; gg8 = r2; go8 = r3;
            jl = tig >> 1;
        } else {
            gi0 = r0; gf0 = r1; gi8 = r2; gf8 = r3;
            gg0 = D1[0]; go0 = D1[1]; gg8 = D1[2]; go8 = D1[3];
            jl = (tig >> 1) + 2;
        }
        int jlg = nh * 4 + jl;            // 0..7: hidden col within CTA
        float4 bi = ((const float4*)(smem + (enc ? OFF_BE : OFF_BD)))[jlg];
        float iv0 = sigf(gi0 + bi.x), fv0 = sigf(gf0 + bi.y);
        float gv0 = tanhfast(gg0 + bi.z), ov0 = sigf(go0 + bi.w);
        float iv8 = sigf(gi8 + bi.x), fv8 = sigf(gf8 + bi.y);
        float gv8 = tanhfast(gg8 + bi.z), ov8 = sigf(go8 + bi.w);
        c0s = fv0 * c0s + iv0 * gv0;
        c8s = fv8 * c8s + iv8 * gv8;
        float h0 = ov0 * tanhfast(c0s);
        float h8 = ov8 * tanhfast(c8s);

        int b0r = (mw << 4) + gid;
        uint32_t colb = (uint32_t)((((cid & 7) << 3) + jlg) << 1);
        uint32_t o0 = sw128((uint32_t)(b0r * 128) + colb);
        uint32_t o8 = sw128((uint32_t)((b0r + 8) * 128) + colb);
        int nb2 = (s + 1) & 1;
        size_t tb = (size_t)gidx * 16384;
        *(__half*)(g_hh[nb2] + tb + o0) = __float2half_rn(h0);
        *(__half*)(g_hh[nb2] + tb + o8) = __float2half_rn(h8);
        if (s >= TT - 1 && s < 2 * TT - 1) {
            int kd = s - (TT - 1);
            float* hb = g_hist + ((size_t)kd * HH + (jb + jlg)) * BB;
            hb[b0r] = h0;
            hb[b0r + 8] = h8;
        }
        __syncthreads();
        if (tid == 0) {
            __threadfence();
            atomicAdd(&g_flag[gidx], 1u);
        }
    }
}

// ============ final y pass: out[b][T-1-kd][:] = hist[kd]·w_outT + b_out ============
__global__ void __launch_bounds__(128) y_final(const float* __restrict__ b_out,
                                               float* __restrict__ out) {
    const int kd = blockIdx.x;
    const int b = threadIdx.x;
    ull acc[32];
#pragma unroll
    for (int q = 0; q < 32; ++q) {
        float2 bo = *(const float2*)(b_out + 2 * q);
        asm("mov.b64 %0, {%1, %2};" : "=l"(acc[q]) : "f"(bo.x), "f"(bo.y));
    }
    const float* hp = g_hist + (size_t)kd * HH * BB + b;
#pragma unroll 4
    for (int j = 0; j < HH; ++j) {
        float hv = hp[(size_t)j * BB];
        ull h2;
        asm("mov.b64 %0, {%1, %2};" : "=l"(h2) : "f"(hv), "f"(hv));
        const ulonglong2* wp = (const ulonglong2*)(g_woutT + j * FF);
#pragma unroll
        for (int q = 0; q < 16; ++q) {
            ulonglong2 w2 = wp[q];
            asm("fma.rn.f32x2 %0, %1, %2, %0;" : "+l"(acc[2 * q]) : "l"(w2.x), "l"(h2));
            asm("fma.rn.f32x2 %0, %1, %2, %0;" : "+l"(acc[2 * q + 1]) : "l"(w2.y), "l"(h2));
        }
    }
    float* dst = out + ((size_t)b * TT + (TT - 1 - kd)) * FF;
#pragma unroll
    for (int q = 0; q < 16; ++q) {
        float2 a = *(float2*)&acc[2 * q];
        float2 bq = *(float2*)&acc[2 * q + 1];
        *(float4*)(dst + 4 * q) = make_float4(a.x, a.y, bq.x, bq.y);
    }
}

// ---------------- launch ----------------
extern "C" void kernel_launch(void* const* d_in, const int* in_sizes, int n_in,
                              void* d_out, int out_size) {
    (void)in_sizes; (void)n_in; (void)out_size;
    const float* ts       = (const float*)d_in[0];
    const float* w_ih_enc = (const float*)d_in[1];
    const float* w_hh_enc = (const float*)d_in[2];
    const float* b_ih_enc = (const float*)d_in[3];
    const float* b_hh_enc = (const float*)d_in[4];
    const float* w_ih_dec = (const float*)d_in[5];
    const float* w_hh_dec = (const float*)d_in[6];
    const float* b_ih_dec = (const float*)d_in[7];
    const float* b_hh_dec = (const float*)d_in[8];
    const float* w_out    = (const float*)d_in[9];
    const float* b_out    = (const float*)d_in[10];
    float* out = (float*)d_out;

    static bool attr_set = false;
    if (!attr_set) {
        cudaFuncSetAttribute(lstm_persistent,
                             cudaFuncAttributeMaxDynamicSharedMemorySize, SMEM_BYTES);
        attr_set = true;
    }
    reset_flags_kernel<<<1, 32>>>();
    lstm_persistent<<<NB, NT, SMEM_BYTES>>>(
        ts, w_ih_enc, w_hh_enc, b_ih_enc, b_hh_enc,
        w_ih_dec, w_hh_dec, b_ih_dec, b_hh_dec, w_out, b_out, out);
    y_final<<<TT, 128>>>(b_out, out);
}

// round 13
// speedup vs baseline: 1.3121x; 1.3121x over previous
#include <cuda_runtime.h>
#include <cuda_fp16.h>
#include <cstdint>

#define NB 128
#define NT 256          // 8 compute warps
#define BB 128
#define TT 1024
#define FF 64
#define HH 512

typedef unsigned long long ull;

// ---------------- device scratch ----------------
__device__ __align__(1024) unsigned char g_hh[2][8 * 16384];     // h fp16 chunk tiles
__device__ __align__(1024) unsigned char g_xh[(size_t)TT * 16384]; // x fp16 tiles
__device__ float g_hist[(size_t)TT * HH * BB];   // decoder-input h [kd][j][b]
__device__ float g_woutT[HH * FF];
__device__ unsigned int g_flag[8];
__device__ unsigned int g_count = 0, g_gen = 0;

// ---------------- smem byte offsets ----------------
#define OFF_WBE  0          // enc B frags: 9 ch * 4096
#define OFF_WBD  36864      // dec B frags: 8 ch * 4096
#define OFF_A    69632      // 3 stages * 32768 (2 chunks each)
#define OFF_BE   167936     // 16 floats
#define OFF_BD   168000     // 16 floats
#define SMEM_BYTES 168064

static __device__ __forceinline__ uint32_t sw128(uint32_t o) {
    return o ^ ((o >> 3) & 0x70);
}
__device__ __forceinline__ float sigf(float x) {
    return __fdividef(1.0f, 1.0f + __expf(-x));
}
__device__ __forceinline__ float tanhfast(float x) {
    return 1.0f - __fdividef(2.0f, __expf(2.0f * x) + 1.0f);
}

__device__ __forceinline__ void grid_barrier_init() {
    __syncthreads();
    if (threadIdx.x == 0) {
        unsigned int cur0;
        asm volatile("ld.acquire.gpu.b32 %0, [%1];" : "=r"(cur0) : "l"(&g_gen) : "memory");
        unsigned int target = cur0 + 1u;
        __threadfence();
        unsigned int t = atomicAdd(&g_count, 1u);
        if (t == NB - 1u) {
            g_count = 0u;
            asm volatile("st.release.gpu.b32 [%0], %1;" :: "l"(&g_gen), "r"(target) : "memory");
        } else {
            unsigned int cur;
            do {
                __nanosleep(20);
                asm volatile("ld.acquire.gpu.b32 %0, [%1];" : "=r"(cur) : "l"(&g_gen) : "memory");
            } while ((int)(cur - target) < 0);
        }
    }
    __syncthreads();
}
__device__ __forceinline__ void wait_flag(int ch, unsigned int tgt) {
    unsigned int v;
    asm volatile("ld.acquire.gpu.b32 %0, [%1];" : "=r"(v) : "l"(&g_flag[ch]) : "memory");
    while ((int)(v - tgt) < 0) {
        __nanosleep(32);
        asm volatile("ld.acquire.gpu.b32 %0, [%1];" : "=r"(v) : "l"(&g_flag[ch]) : "memory");
    }
}

// stage 1 or 2 fp16 chunks (16KB each) into a 32KB stage buffer, one commit group
__device__ __forceinline__ void prefetch_stage(uint32_t dst, const unsigned char* a,
                                               const unsigned char* b, int tid) {
#pragma unroll
    for (int i = 0; i < 4; i++) {
        uint32_t off = (uint32_t)(tid + NT * i) * 16u;
        asm volatile("cp.async.cg.shared.global [%0], [%1], 16;"
                     :: "r"(dst + off), "l"(a + off) : "memory");
    }
    if (b) {
#pragma unroll
        for (int i = 0; i < 4; i++) {
            uint32_t off = (uint32_t)(tid + NT * i) * 16u;
            asm volatile("cp.async.cg.shared.global [%0], [%1], 16;"
                         :: "r"(dst + 16384u + off), "l"(b + off) : "memory");
        }
    }
    asm volatile("cp.async.commit_group;" ::: "memory");
}

__device__ __forceinline__ void ldmx4(uint32_t addr, uint32_t* a) {
    asm volatile("ldmatrix.sync.aligned.m8n8.x4.shared.b16 {%0,%1,%2,%3}, [%4];"
                 : "=r"(a[0]), "=r"(a[1]), "=r"(a[2]), "=r"(a[3]) : "r"(addr));
}
__device__ __forceinline__ void mma16816(float* d, const uint32_t* a, uint32_t b0, uint32_t b1) {
    asm volatile(
        "mma.sync.aligned.m16n8k16.row.col.f32.f16.f16.f32 "
        "{%0,%1,%2,%3}, {%4,%5,%6,%7}, {%8,%9}, {%0,%1,%2,%3};"
        : "+f"(d[0]), "+f"(d[1]), "+f"(d[2]), "+f"(d[3])
        : "r"(a[0]), "r"(a[1]), "r"(a[2]), "r"(a[3]), "r"(b0), "r"(b1));
}
__device__ __forceinline__ uint32_t pack_h2(float lo, float hi) {
    uint32_t r;
    asm("cvt.rn.f16x2.f32 %0, %1, %2;" : "=r"(r) : "f"(hi), "f"(lo));
    return r;
}

// consume one staged 16KB chunk: 4 ldmatrix + 16 LDS.64 + 16 HMMA
__device__ __forceinline__ void consume_chunk(uint32_t sa, uint32_t wb,
                                              uint32_t abase, int lane,
                                              float* D0, float* D1) {
#pragma unroll
    for (int ks = 0; ks < 4; ++ks) {
        uint32_t ao = sw128(abase + (uint32_t)ks * 32u);
        uint32_t a[4];
        ldmx4(sa + ao, a);
#pragma unroll
        for (int nt = 0; nt < 2; ++nt) {
            uint32_t fb = wb + (uint32_t)(ks * 2 + nt) * 512u + (uint32_t)lane * 8u;
            uint32_t bh0, bh1, bl0, bl1;
            asm("ld.shared.v2.b32 {%0,%1}, [%2];" : "=r"(bh0), "=r"(bh1) : "r"(fb));
            asm("ld.shared.v2.b32 {%0,%1}, [%2];" : "=r"(bl0), "=r"(bl1) : "r"(fb + 256u));
            float* D = nt ? D1 : D0;
            mma16816(D, a, bh0, bh1);
            mma16816(D, a, bl0, bl1);
        }
    }
}

__global__ void reset_flags_kernel() {
    if (threadIdx.x < 8) g_flag[threadIdx.x] = 16u;   // h_0 ready baseline
}

__global__ void __launch_bounds__(NT, 1) lstm_persistent(
    const float* __restrict__ ts,
    const float* __restrict__ w_ih_enc, const float* __restrict__ w_hh_enc,
    const float* __restrict__ b_ih_enc, const float* __restrict__ b_hh_enc,
    const float* __restrict__ w_ih_dec, const float* __restrict__ w_hh_dec,
    const float* __restrict__ b_ih_dec, const float* __restrict__ b_hh_dec,
    const float* __restrict__ w_out, const float* __restrict__ b_out,
    float* __restrict__ out)
{
    extern __shared__ unsigned char smem[];
    const int tid = threadIdx.x;
    const int cid = blockIdx.x;
    const int jb = cid * 4;
    const int gidx = cid >> 4;
    const uint32_t sb = (uint32_t)__cvta_generic_to_shared(smem);

    // ======== INIT: encoder B fragments, fp16 hi + residual lo ========
    for (int e = tid; e < 9 * 4 * 2 * 32; e += NT) {
        int lane = e & 31, rem = e >> 5;
        int nt = rem & 1, ks = (rem >> 1) & 3, ch = rem >> 3;
        int gid = lane >> 2, tig = lane & 3;
        int n = nt * 8 + gid, jl = n >> 2, q = n & 3;
        int row = q * HH + jb + jl;
        float v[4];
#pragma unroll
        for (int d = 0; d < 4; ++d) {
            int kin = ks * 16 + 2 * tig + ((d & 2) ? 8 : 0) + (d & 1);
            v[d] = (ch < 8) ? w_hh_enc[(size_t)row * HH + ch * 64 + kin]
                            : w_ih_enc[(size_t)row * FF + kin];
        }
        float hi[4], lo[4];
#pragma unroll
        for (int d = 0; d < 4; ++d) {
            hi[d] = __half2float(__float2half_rn(v[d]));
            lo[d] = v[d] - hi[d];
        }
        uint32_t base = (uint32_t)(ch * 8 + ks * 2 + nt) * 512u + (uint32_t)lane * 8u;
        uint32_t* ph = (uint32_t*)(smem + OFF_WBE + base);
        uint32_t* pl = (uint32_t*)(smem + OFF_WBE + base + 256);
        ph[0] = pack_h2(hi[0], hi[1]); ph[1] = pack_h2(hi[2], hi[3]);
        pl[0] = pack_h2(lo[0], lo[1]); pl[1] = pack_h2(lo[2], lo[3]);
    }
    // ======== INIT: decoder fused B fragments (W_eff = w_hh + w_ih @ w_out) ========
    for (int e = tid; e < 8 * 4 * 2 * 32; e += NT) {
        int lane = e & 31, rem = e >> 5;
        int nt = rem & 1, ks = (rem >> 1) & 3, ch = rem >> 3;
        int gid = lane >> 2, tig = lane & 3;
        int n = nt * 8 + gid, jl = n >> 2, q = n & 3;
        int row = q * HH + jb + jl;
        const float* wr = w_ih_dec + (size_t)row * FF;
        float v[4];
#pragma unroll
        for (int d = 0; d < 4; ++d) {
            int k = ch * 64 + ks * 16 + 2 * tig + ((d & 2) ? 8 : 0) + (d & 1);
            float acc = w_hh_dec[(size_t)row * HH + k];
#pragma unroll 8
            for (int f = 0; f < FF; ++f) acc += wr[f] * w_out[(size_t)f * HH + k];
            v[d] = acc;
        }
        float hi[4], lo[4];
#pragma unroll
        for (int d = 0; d < 4; ++d) {
            hi[d] = __half2float(__float2half_rn(v[d]));
            lo[d] = v[d] - hi[d];
        }
        uint32_t base = (uint32_t)(ch * 8 + ks * 2 + nt) * 512u + (uint32_t)lane * 8u;
        uint32_t* ph = (uint32_t*)(smem + OFF_WBD + base);
        uint32_t* pl = (uint32_t*)(smem + OFF_WBD + base + 256);
        ph[0] = pack_h2(hi[0], hi[1]); ph[1] = pack_h2(hi[2], hi[3]);
        pl[0] = pack_h2(lo[0], lo[1]); pl[1] = pack_h2(lo[2], lo[3]);
    }
    // biases [jl][q]
    if (tid < 16) {
        int jl = tid >> 2, q = tid & 3;
        int row = q * HH + jb + jl;
        ((float*)(smem + OFF_BE))[jl * 4 + q] = b_ih_enc[row] + b_hh_enc[row];
        float v = b_ih_dec[row] + b_hh_dec[row];
        const float* wr = w_ih_dec + (size_t)row * FF;
#pragma unroll 8
        for (int f = 0; f < FF; ++f) v += wr[f] * b_out[f];
        ((float*)(smem + OFF_BD))[jl * 4 + q] = v;
    }
    // x tiles: [t][b*128B] fp16, swizzled; 8 t per CTA
    for (int tt = 0; tt < TT / NB; ++tt) {
        int t = cid * (TT / NB) + tt;
        for (int idx = tid; idx < BB * 16; idx += NT) {
            int b = idx >> 4, f4 = (idx & 15) * 4;
            float v0 = ts[((size_t)b * TT + t) * FF + f4];
            float v1 = ts[((size_t)b * TT + t) * FF + f4 + 1];
            float v2 = ts[((size_t)b * TT + t) * FF + f4 + 2];
            float v3 = ts[((size_t)b * TT + t) * FF + f4 + 3];
            uint32_t o = sw128((uint32_t)(b * 128 + f4 * 2));
            *(uint2*)(g_xh + (size_t)t * 16384 + o) =
                make_uint2(pack_h2(v0, v1), pack_h2(v2, v3));
        }
    }
    // zero own h_0 slice (4 cols x 128 b)
    if (tid < 128) {
        uint32_t o = sw128((uint32_t)(tid * 128 + (cid & 15) * 8));
        *(uint2*)(g_hh[0] + (size_t)gidx * 16384 + o) = make_uint2(0, 0);
    }
    if (cid == 0) {
        for (int idx = tid; idx < HH * FF; idx += NT) {
            int j = idx >> 6, f = idx & 63;
            g_woutT[j * FF + f] = w_out[(size_t)f * HH + j];
        }
    }
    grid_barrier_init();

    // ======== persistent recurrence ========
    const int w = tid >> 5, lane = tid & 31;
    const int gid = lane >> 2, tig = lane & 3;
    const uint32_t abase = (uint32_t)(((w << 4) + (lane & 15)) * 128 + ((lane >> 4) & 1) * 16);

    float c0s = 0.0f, c8s = 0.0f;

    for (int s = 0; s < 2 * TT; ++s) {
        const bool enc = (s < TT);
        const int nc = enc ? 9 : 8;
        const int nst = (nc + 1) >> 1;   // 5 enc, 4 dec
        if (s == TT) { c0s = 0.0f; c8s = 0.0f; }
        const unsigned int tgt = 16u * (unsigned)(s + 1);
        const unsigned char* hh = g_hh[s & 1];

        // rotated chunk order: enc: [x, h(g), h(g+1), ...] ; dec: [h(g), h(g+1), ...]
        // weight chunk id for order index i:
#define WCH(i) (enc ? ((i) == 0 ? 8 : ((gidx + (i) - 1) & 7)) : ((gidx + (i)) & 7))
#define SRC(i) (enc ? ((i) == 0 ? g_xh + (size_t)s * 16384 \
                                : hh + (size_t)((gidx + (i) - 1) & 7) * 16384) \
                    : hh + (size_t)((gidx + (i)) & 7) * 16384)
#define ISH(i) (!enc || (i) > 0)

        // prologue flag waits: chunks 0..3 (threads 0..3, parallel)
        if (tid < 4 && tid < nc && ISH(tid)) wait_flag(WCH(tid), tgt);
        __syncthreads();

        prefetch_stage(sb + OFF_A, SRC(0), (1 < nc) ? SRC(1) : nullptr, tid);
        prefetch_stage(sb + OFF_A + 32768u, SRC(2), (3 < nc) ? SRC(3) : nullptr, tid);

        float D0[4] = {0, 0, 0, 0}, D1[4] = {0, 0, 0, 0};

        for (int st = 0; st < nst; ++st) {
            if (st + 2 < nst) {
                // deferred flag waits for stage st+2's chunks (threads 0,1)
                if (tid < 2) {
                    int i = 2 * (st + 2) + tid;
                    if (i < nc) wait_flag(WCH(i), tgt);   // always h chunks here (i>=4)
                }
            }
            if (st < nst - 1) {
                asm volatile("cp.async.wait_group 1;" ::: "memory");
            } else {
                asm volatile("cp.async.wait_group 0;" ::: "memory");
            }
            __syncthreads();   // stage st landed everywhere; buffer (st+2)%3 free
            if (st + 2 < nst) {
                int i = 2 * (st + 2);
                prefetch_stage(sb + OFF_A + (uint32_t)((st + 2) % 3) * 32768u,
                               SRC(i), (i + 1 < nc) ? SRC(i + 1) : nullptr, tid);
            }
            uint32_t sa = sb + OFF_A + (uint32_t)(st % 3) * 32768u;
            int i0 = 2 * st;
            {
                uint32_t wb = sb + (enc ? OFF_WBE : OFF_WBD) + (uint32_t)WCH(i0) * 4096u;
                consume_chunk(sa, wb, abase, lane, D0, D1);
            }
            if (i0 + 1 < nc) {
                uint32_t wb = sb + (enc ? OFF_WBE : OFF_WBD) + (uint32_t)WCH(i0 + 1) * 4096u;
                consume_chunk(sa + 16384u, wb, abase, lane, D0, D1);
            }
        }
#undef WCH
#undef SRC
#undef ISH

        // ---- epilogue: gate pairing via shfl, cell update ----
        bool ev = ((tig & 1) == 0);
        float s0 = ev ? D1[0] : D0[0];
        float s1 = ev ? D1[1] : D0[1];
        float s2 = ev ? D1[2] : D0[2];
        float s3 = ev ? D1[3] : D0[3];
        float r0 = __shfl_xor_sync(0xffffffffu, s0, 1);
        float r1 = __shfl_xor_sync(0xffffffffu, s1, 1);
        float r2 = __shfl_xor_sync(0xffffffffu, s2, 1);
        float r3 = __shfl_xor_sync(0xffffffffu, s3, 1);
        float gi0, gf0, gi8, gf8, gg0, go0, gg8, go8;
        int jl;
        if (ev) {
            gi0 = D0[0]; gf0 = D0[1]; gi8 = D0[2]; gf8 = D0[3];
            gg0 = r0; go0 = r1; gg8 = r2; go8 = r3;
            jl = tig >> 1;
        } else {
            gi0 = r0; gf0 = r1; gi8 = r2; gf8 = r3;
            gg0 = D1[0]; go0 = D1[1]; gg8 = D1[2]; go8 = D1[3];
            jl = (tig >> 1) + 2;
        }
        float4 bi = ((const float4*)(smem + (enc ? OFF_BE : OFF_BD)))[jl];
        float iv0 = sigf(gi0 + bi.x), fv0 = sigf(gf0 + bi.y);
        float gv0 = tanhfast(gg0 + bi.z), ov0 = sigf(go0 + bi.w);
        float iv8 = sigf(gi8 + bi.x), fv8 = sigf(gf8 + bi.y);
        float gv8 = tanhfast(gg8 + bi.z), ov8 = sigf(go8 + bi.w);
        c0s = fv0 * c0s + iv0 * gv0;
        c8s = fv8 * c8s + iv8 * gv8;
        float h0 = ov0 * tanhfast(c0s);
        float h8 = ov8 * tanhfast(c8s);

        int b0r = (w << 4) + gid;
        uint32_t colb = (uint32_t)((((cid & 15) << 2) + jl) << 1);
        uint32_t o0 = sw128((uint32_t)(b0r * 128) + colb);
        uint32_t o8 = sw128((uint32_t)((b0r + 8) * 128) + colb);
        int nb2 = (s + 1) & 1;
        size_t tb = (size_t)gidx * 16384;
        *(__half*)(g_hh[nb2] + tb + o0) = __float2half_rn(h0);
        *(__half*)(g_hh[nb2] + tb + o8) = __float2half_rn(h8);
        if (s >= TT - 1 && s < 2 * TT - 1) {
            int kd = s - (TT - 1);
            float* hb = g_hist + ((size_t)kd * HH + (jb + jl)) * BB;
            hb[b0r] = h0;
            hb[b0r + 8] = h8;
        }
        __syncthreads();
        if (tid == 0) {
            __threadfence();
            atomicAdd(&g_flag[gidx], 1u);
        }
    }
}

// ============ final y pass: out[b][T-1-kd][:] = hist[kd]·w_outT + b_out ============
__global__ void __launch_bounds__(128) y_final(const float* __restrict__ b_out,
                                               float* __restrict__ out) {
    const int kd = blockIdx.x;
    const int b = threadIdx.x;
    ull acc[32];
#pragma unroll
    for (int q = 0; q < 32; ++q) {
        float2 bo = *(const float2*)(b_out + 2 * q);
        asm("mov.b64 %0, {%1, %2};" : "=l"(acc[q]) : "f"(bo.x), "f"(bo.y));
    }
    const float* hp = g_hist + (size_t)kd * HH * BB + b;
#pragma unroll 4
    for (int j = 0; j < HH; ++j) {
        float hv = hp[(size_t)j * BB];
        ull h2;
        asm("mov.b64 %0, {%1, %2};" : "=l"(h2) : "f"(hv), "f"(hv));
        const ulonglong2* wp = (const ulonglong2*)(g_woutT + j * FF);
#pragma unroll
        for (int q = 0; q < 16; ++q) {
            ulonglong2 w2 = wp[q];
            asm("fma.rn.f32x2 %0, %1, %2, %0;" : "+l"(acc[2 * q]) : "l"(w2.x), "l"(h2));
            asm("fma.rn.f32x2 %0, %1, %2, %0;" : "+l"(acc[2 * q + 1]) : "l"(w2.y), "l"(h2));
        }
    }
    float* dst = out + ((size_t)b * TT + (TT - 1 - kd)) * FF;
#pragma unroll
    for (int q = 0; q < 16; ++q) {
        float2 a = *(float2*)&acc[2 * q];
        float2 bq = *(float2*)&acc[2 * q + 1];
        *(float4*)(dst + 4 * q) = make_float4(a.x, a.y, bq.x, bq.y);
    }
}

// ---------------- launch ----------------
extern "C" void kernel_launch(void* const* d_in, const int* in_sizes, int n_in,
                              void* d_out, int out_size) {
    (void)in_sizes; (void)n_in; (void)out_size;
    const float* ts       = (const float*)d_in[0];
    const float* w_ih_enc = (const float*)d_in[1];
    const float* w_hh_enc = (const float*)d_in[2];
    const float* b_ih_enc = (const float*)d_in[3];
    const float* b_hh_enc = (const float*)d_in[4];
    const float* w_ih_dec = (const float*)d_in[5];
    const float* w_hh_dec = (const float*)d_in[6];
    const float* b_ih_dec = (const float*)d_in[7];
    const float* b_hh_dec = (const float*)d_in[8];
    const float* w_out    = (const float*)d_in[9];
    const float* b_out    = (const float*)d_in[10];
    float* out = (float*)d_out;

    static bool attr_set = false;
    if (!attr_set) {
        cudaFuncSetAttribute(lstm_persistent,
                             cudaFuncAttributeMaxDynamicSharedMemorySize, SMEM_BYTES);
        attr_set = true;
    }
    reset_flags_kernel<<<1, 32>>>();
    lstm_persistent<<<NB, NT, SMEM_BYTES>>>(
        ts, w_ih_enc, w_hh_enc, b_ih_enc, b_hh_enc,
        w_ih_dec, w_hh_dec, b_ih_dec, b_hh_dec, w_out, b_out, out);
    y_final<<<TT, 128>>>(b_out, out);
}

// round 14
// speedup vs baseline: 1.3283x; 1.0123x over previous
#include <cuda_runtime.h>
#include <cuda_fp16.h>
#include <cstdint>

#define NB 128
#define NT 512          // 16 warps: 8 m-positions x 2 k-sets
#define BB 128
#define TT 1024
#define FF 64
#define HH 512

typedef unsigned long long ull;

// ---------------- device scratch ----------------
__device__ __align__(1024) unsigned char g_hh[2][8 * 16384];     // h fp16 chunk tiles
__device__ __align__(1024) unsigned char g_xh[(size_t)TT * 16384]; // x fp16 tiles
__device__ float g_hist[(size_t)TT * HH * BB];   // decoder-input h [kd][j][b]
__device__ float g_woutT[HH * FF];
__device__ unsigned int g_flag[8];
__device__ unsigned int g_count = 0, g_gen = 0;

// ---------------- smem byte offsets ----------------
#define OFF_WBE  0          // enc B frags: 9 ch * 4096
#define OFF_WBD  36864      // dec B frags: 8 ch * 4096
#define OFF_A    69632      // 3 stages * 16384
#define OFF_RED  118784     // 8KB: cross-kset reduction [q 0..7][256 threads]
#define OFF_BE   126976     // 16 floats
#define OFF_BD   127040     // 16 floats
#define SMEM_BYTES 127104

static __device__ __forceinline__ uint32_t sw128(uint32_t o) {
    return o ^ ((o >> 3) & 0x70);
}
__device__ __forceinline__ float sigf(float x) {
    return __fdividef(1.0f, 1.0f + __expf(-x));
}
__device__ __forceinline__ float tanhfast(float x) {
    return 1.0f - __fdividef(2.0f, __expf(2.0f * x) + 1.0f);
}

__device__ __forceinline__ void grid_barrier_init() {
    __syncthreads();
    if (threadIdx.x == 0) {
        unsigned int cur0;
        asm volatile("ld.acquire.gpu.b32 %0, [%1];" : "=r"(cur0) : "l"(&g_gen) : "memory");
        unsigned int target = cur0 + 1u;
        __threadfence();
        unsigned int t = atomicAdd(&g_count, 1u);
        if (t == NB - 1u) {
            g_count = 0u;
            asm volatile("st.release.gpu.b32 [%0], %1;" :: "l"(&g_gen), "r"(target) : "memory");
        } else {
            unsigned int cur;
            do {
                __nanosleep(20);
                asm volatile("ld.acquire.gpu.b32 %0, [%1];" : "=r"(cur) : "l"(&g_gen) : "memory");
            } while ((int)(cur - target) < 0);
        }
    }
    __syncthreads();
}
__device__ __forceinline__ void wait_flag(int ch, unsigned int tgt) {
    unsigned int v;
    asm volatile("ld.acquire.gpu.b32 %0, [%1];" : "=r"(v) : "l"(&g_flag[ch]) : "memory");
    while ((int)(v - tgt) < 0) {
        __nanosleep(32);
        asm volatile("ld.acquire.gpu.b32 %0, [%1];" : "=r"(v) : "l"(&g_flag[ch]) : "memory");
    }
}

// stage one 16KB fp16 chunk: 2 cp.async.cg per thread (512 threads)
__device__ __forceinline__ void prefetch_chunk(uint32_t dst, const unsigned char* src, int tid) {
#pragma unroll
    for (int i = 0; i < 2; i++) {
        uint32_t off = (uint32_t)(tid + NT * i) * 16u;
        asm volatile("cp.async.cg.shared.global [%0], [%1], 16;"
                     :: "r"(dst + off), "l"(src + off) : "memory");
    }
    asm volatile("cp.async.commit_group;" ::: "memory");
}

__device__ __forceinline__ void ldmx4(uint32_t addr, uint32_t* a) {
    asm volatile("ldmatrix.sync.aligned.m8n8.x4.shared.b16 {%0,%1,%2,%3}, [%4];"
                 : "=r"(a[0]), "=r"(a[1]), "=r"(a[2]), "=r"(a[3]) : "r"(addr));
}
__device__ __forceinline__ void mma16816(float* d, const uint32_t* a, uint32_t b0, uint32_t b1) {
    asm volatile(
        "mma.sync.aligned.m16n8k16.row.col.f32.f16.f16.f32 "
        "{%0,%1,%2,%3}, {%4,%5,%6,%7}, {%8,%9}, {%0,%1,%2,%3};"
        : "+f"(d[0]), "+f"(d[1]), "+f"(d[2]), "+f"(d[3])
        : "r"(a[0]), "r"(a[1]), "r"(a[2]), "r"(a[3]), "r"(b0), "r"(b1));
}
__device__ __forceinline__ uint32_t pack_h2(float lo, float hi) {
    uint32_t r;
    asm("cvt.rn.f16x2.f32 %0, %1, %2;" : "=r"(r) : "f"(hi), "f"(lo));
    return r;
}

// consume this warp's k-half of one staged chunk: 2 ldmatrix + 8 LDS.64 + 8 HMMA
__device__ __forceinline__ void consume_chunk(uint32_t sa, uint32_t wb,
                                              uint32_t abase, int lane, int kset,
                                              float* D0, float* D1) {
#pragma unroll
    for (int ksl = 0; ksl < 2; ++ksl) {
        int ks = kset * 2 + ksl;
        uint32_t ao = sw128(abase + (uint32_t)ks * 32u);
        uint32_t a[4];
        ldmx4(sa + ao, a);
#pragma unroll
        for (int nt = 0; nt < 2; ++nt) {
            uint32_t fb = wb + (uint32_t)(ks * 2 + nt) * 512u + (uint32_t)lane * 8u;
            uint32_t bh0, bh1, bl0, bl1;
            asm("ld.shared.v2.b32 {%0,%1}, [%2];" : "=r"(bh0), "=r"(bh1) : "r"(fb));
            asm("ld.shared.v2.b32 {%0,%1}, [%2];" : "=r"(bl0), "=r"(bl1) : "r"(fb + 256u));
            float* D = nt ? D1 : D0;
            mma16816(D, a, bh0, bh1);
            mma16816(D, a, bl0, bl1);
        }
    }
}

__global__ void reset_flags_kernel() {
    if (threadIdx.x < 8) g_flag[threadIdx.x] = 16u;   // h_0 ready baseline
}

__global__ void __launch_bounds__(NT, 1) lstm_persistent(
    const float* __restrict__ ts,
    const float* __restrict__ w_ih_enc, const float* __restrict__ w_hh_enc,
    const float* __restrict__ b_ih_enc, const float* __restrict__ b_hh_enc,
    const float* __restrict__ w_ih_dec, const float* __restrict__ w_hh_dec,
    const float* __restrict__ b_ih_dec, const float* __restrict__ b_hh_dec,
    const float* __restrict__ w_out, const float* __restrict__ b_out,
    float* __restrict__ out)
{
    extern __shared__ unsigned char smem[];
    const int tid = threadIdx.x;
    const int cid = blockIdx.x;
    const int jb = cid * 4;
    const int gidx = cid >> 4;
    const uint32_t sb = (uint32_t)__cvta_generic_to_shared(smem);

    // ======== INIT: encoder B fragments, fp16 hi + residual lo ========
    for (int e = tid; e < 9 * 4 * 2 * 32; e += NT) {
        int lane = e & 31, rem = e >> 5;
        int nt = rem & 1, ks = (rem >> 1) & 3, ch = rem >> 3;
        int gid = lane >> 2, tig = lane & 3;
        int n = nt * 8 + gid, jl = n >> 2, q = n & 3;
        int row = q * HH + jb + jl;
        float v[4];
#pragma unroll
        for (int d = 0; d < 4; ++d) {
            int kin = ks * 16 + 2 * tig + ((d & 2) ? 8 : 0) + (d & 1);
            v[d] = (ch < 8) ? w_hh_enc[(size_t)row * HH + ch * 64 + kin]
                            : w_ih_enc[(size_t)row * FF + kin];
        }
        float hi[4], lo[4];
#pragma unroll
        for (int d = 0; d < 4; ++d) {
            hi[d] = __half2float(__float2half_rn(v[d]));
            lo[d] = v[d] - hi[d];
        }
        uint32_t base = (uint32_t)(ch * 8 + ks * 2 + nt) * 512u + (uint32_t)lane * 8u;
        uint32_t* ph = (uint32_t*)(smem + OFF_WBE + base);
        uint32_t* pl = (uint32_t*)(smem + OFF_WBE + base + 256);
        ph[0] = pack_h2(hi[0], hi[1]); ph[1] = pack_h2(hi[2], hi[3]);
        pl[0] = pack_h2(lo[0], lo[1]); pl[1] = pack_h2(lo[2], lo[3]);
    }
    // ======== INIT: decoder fused B fragments (W_eff = w_hh + w_ih @ w_out) ========
    for (int e = tid; e < 8 * 4 * 2 * 32; e += NT) {
        int lane = e & 31, rem = e >> 5;
        int nt = rem & 1, ks = (rem >> 1) & 3, ch = rem >> 3;
        int gid = lane >> 2, tig = lane & 3;
        int n = nt * 8 + gid, jl = n >> 2, q = n & 3;
        int row = q * HH + jb + jl;
        const float* wr = w_ih_dec + (size_t)row * FF;
        float v[4];
#pragma unroll
        for (int d = 0; d < 4; ++d) {
            int k = ch * 64 + ks * 16 + 2 * tig + ((d & 2) ? 8 : 0) + (d & 1);
            float acc = w_hh_dec[(size_t)row * HH + k];
#pragma unroll 8
            for (int f = 0; f < FF; ++f) acc += wr[f] * w_out[(size_t)f * HH + k];
            v[d] = acc;
        }
        float hi[4], lo[4];
#pragma unroll
        for (int d = 0; d < 4; ++d) {
            hi[d] = __half2float(__float2half_rn(v[d]));
            lo[d] = v[d] - hi[d];
        }
        uint32_t base = (uint32_t)(ch * 8 + ks * 2 + nt) * 512u + (uint32_t)lane * 8u;
        uint32_t* ph = (uint32_t*)(smem + OFF_WBD + base);
        uint32_t* pl = (uint32_t*)(smem + OFF_WBD + base + 256);
        ph[0] = pack_h2(hi[0], hi[1]); ph[1] = pack_h2(hi[2], hi[3]);
        pl[0] = pack_h2(lo[0], lo[1]); pl[1] = pack_h2(lo[2], lo[3]);
    }
    // biases [jl][q]
    if (tid < 16) {
        int jl = tid >> 2, q = tid & 3;
        int row = q * HH + jb + jl;
        ((float*)(smem + OFF_BE))[jl * 4 + q] = b_ih_enc[row] + b_hh_enc[row];
        float v = b_ih_dec[row] + b_hh_dec[row];
        const float* wr = w_ih_dec + (size_t)row * FF;
#pragma unroll 8
        for (int f = 0; f < FF; ++f) v += wr[f] * b_out[f];
        ((float*)(smem + OFF_BD))[jl * 4 + q] = v;
    }
    // x tiles: [t][b*128B] fp16, swizzled; 8 t per CTA
    for (int tt = 0; tt < TT / NB; ++tt) {
        int t = cid * (TT / NB) + tt;
        for (int idx = tid; idx < BB * 16; idx += NT) {
            int b = idx >> 4, f4 = (idx & 15) * 4;
            float v0 = ts[((size_t)b * TT + t) * FF + f4];
            float v1 = ts[((size_t)b * TT + t) * FF + f4 + 1];
            float v2 = ts[((size_t)b * TT + t) * FF + f4 + 2];
            float v3 = ts[((size_t)b * TT + t) * FF + f4 + 3];
            uint32_t o = sw128((uint32_t)(b * 128 + f4 * 2));
            *(uint2*)(g_xh + (size_t)t * 16384 + o) =
                make_uint2(pack_h2(v0, v1), pack_h2(v2, v3));
        }
    }
    // zero own h_0 slice (4 cols x 128 b)
    if (tid < 128) {
        uint32_t o = sw128((uint32_t)(tid * 128 + (cid & 15) * 8));
        *(uint2*)(g_hh[0] + (size_t)gidx * 16384 + o) = make_uint2(0, 0);
    }
    if (cid == 0) {
        for (int idx = tid; idx < HH * FF; idx += NT) {
            int j = idx >> 6, f = idx & 63;
            g_woutT[j * FF + f] = w_out[(size_t)f * HH + j];
        }
    }
    grid_barrier_init();

    // ======== persistent recurrence ========
    const int wid = tid >> 5, lane = tid & 31;
    const int mw = wid & 7, kset = wid >> 3;   // m-position, k-set
    const int gid = lane >> 2, tig = lane & 3;
    const uint32_t abase = (uint32_t)(((mw << 4) + (lane & 15)) * 128 + ((lane >> 4) & 1) * 16);
    const int ridx = mw * 32 + lane;           // 0..255: reduction slot
    float* red = (float*)(smem + OFF_RED);

    float c0s = 0.0f, c8s = 0.0f;

    for (int s = 0; s < 2 * TT; ++s) {
        const bool enc = (s < TT);
        const int nc = enc ? 9 : 8;
        if (s == TT) { c0s = 0.0f; c8s = 0.0f; }
        const unsigned int tgt = 16u * (unsigned)(s + 1);

        if (tid < 8) wait_flag(tid, tgt);    // parallel upfront wait
        __syncthreads();

        const unsigned char* hh = g_hh[s & 1];
#define SRC(i) (enc ? ((i) == 0 ? g_xh + (size_t)s * 16384 : hh + (size_t)((i) - 1) * 16384) \
                    : hh + (size_t)(i) * 16384)

        prefetch_chunk(sb + OFF_A, SRC(0), tid);
        prefetch_chunk(sb + OFF_A + 16384u, SRC(1), tid);

        float D0[4] = {0, 0, 0, 0}, D1[4] = {0, 0, 0, 0};

        for (int i = 0; i < nc; ++i) {
            if (i + 1 < nc) {
                asm volatile("cp.async.wait_group 1;" ::: "memory");
            } else {
                asm volatile("cp.async.wait_group 0;" ::: "memory");
            }
            __syncthreads();   // chunk i landed; stage (i+2)%3 free
            if (i + 2 < nc) {
                prefetch_chunk(sb + OFF_A + (uint32_t)((i + 2) % 3) * 16384u, SRC(i + 2), tid);
            }
            int ch = enc ? (i == 0 ? 8 : i - 1) : i;
            uint32_t wb = sb + (enc ? OFF_WBE : OFF_WBD) + (uint32_t)ch * 4096u;
            consume_chunk(sb + OFF_A + (uint32_t)(i % 3) * 16384u, wb, abase, lane, kset, D0, D1);
        }
#undef SRC

        // ---- cross-kset reduction: set 1 dumps partials, set 0 adds ----
        if (kset == 1) {
#pragma unroll
            for (int q = 0; q < 4; ++q) {
                red[q * 256 + ridx] = D0[q];
                red[(q + 4) * 256 + ridx] = D1[q];
            }
        }
        __syncthreads();
        if (kset == 0) {
#pragma unroll
            for (int q = 0; q < 4; ++q) {
                D0[q] += red[q * 256 + ridx];
                D1[q] += red[(q + 4) * 256 + ridx];
            }

            // ---- epilogue: gate pairing via shfl, cell update (warps 0-7) ----
            bool ev = ((tig & 1) == 0);
            float s0 = ev ? D1[0] : D0[0];
            float s1 = ev ? D1[1] : D0[1];
            float s2 = ev ? D1[2] : D0[2];
            float s3 = ev ? D1[3] : D0[3];
            float r0 = __shfl_xor_sync(0xffffffffu, s0, 1);
            float r1 = __shfl_xor_sync(0xffffffffu, s1, 1);
            float r2 = __shfl_xor_sync(0xffffffffu, s2, 1);
            float r3 = __shfl_xor_sync(0xffffffffu, s3, 1);
            float gi0, gf0, gi8, gf8, gg0, go0, gg8, go8;
            int jl;
            if (ev) {
                gi0 = D0[0]; gf0 = D0[1]; gi8 = D0[2]; gf8 = D0[3];
                gg0 = r0; go0 = r1; gg8 = r2; go8 = r3;
                jl = tig >> 1;
            } else {
                gi0 = r0; gf0 = r1; gi8 = r2; gf8 = r3;
                gg0 = D1[0]; go0 = D1[1]; gg8 = D1[2]; go8 = D1[3];
                jl = (tig >> 1) + 2;
            }
            float4 bi = ((const float4*)(smem + (enc ? OFF_BE : OFF_BD)))[jl];
            float iv0 = sigf(gi0 + bi.x), fv0 = sigf(gf0 + bi.y);
            float gv0 = tanhfast(gg0 + bi.z), ov0 = sigf(go0 + bi.w);
            float iv8 = sigf(gi8 + bi.x), fv8 = sigf(gf8 + bi.y);
            float gv8 = tanhfast(gg8 + bi.z), ov8 = sigf(go8 + bi.w);
            c0s = fv0 * c0s + iv0 * gv0;
            c8s = fv8 * c8s + iv8 * gv8;
            float h0 = ov0 * tanhfast(c0s);
            float h8 = ov8 * tanhfast(c8s);

            int b0r = (mw << 4) + gid;
            uint32_t colb = (uint32_t)((((cid & 15) << 2) + jl) << 1);
            uint32_t o0 = sw128((uint32_t)(b0r * 128) + colb);
            uint32_t o8 = sw128((uint32_t)((b0r + 8) * 128) + colb);
            int nb2 = (s + 1) & 1;
            size_t tb = (size_t)gidx * 16384;
            *(__half*)(g_hh[nb2] + tb + o0) = __float2half_rn(h0);
            *(__half*)(g_hh[nb2] + tb + o8) = __float2half_rn(h8);
            if (s >= TT - 1 && s < 2 * TT - 1) {
                int kd = s - (TT - 1);
                float* hb = g_hist + ((size_t)kd * HH + (jb + jl)) * BB;
                hb[b0r] = h0;
                hb[b0r + 8] = h8;
            }
        }
        __syncthreads();
        if (tid == 0) {
            __threadfence();
            atomicAdd(&g_flag[gidx], 1u);
        }
    }
}

// ============ final y pass: out[b][T-1-kd][:] = hist[kd]·w_outT + b_out ============
__global__ void __launch_bounds__(128) y_final(const float* __restrict__ b_out,
                                               float* __restrict__ out) {
    const int kd = blockIdx.x;
    const int b = threadIdx.x;
    ull acc[32];
#pragma unroll
    for (int q = 0; q < 32; ++q) {
        float2 bo = *(const float2*)(b_out + 2 * q);
        asm("mov.b64 %0, {%1, %2};" : "=l"(acc[q]) : "f"(bo.x), "f"(bo.y));
    }
    const float* hp = g_hist + (size_t)kd * HH * BB + b;
#pragma unroll 4
    for (int j = 0; j < HH; ++j) {
        float hv = hp[(size_t)j * BB];
        ull h2;
        asm("mov.b64 %0, {%1, %2};" : "=l"(h2) : "f"(hv), "f"(hv));
        const ulonglong2* wp = (const ulonglong2*)(g_woutT + j * FF);
#pragma unroll
        for (int q = 0; q < 16; ++q) {
            ulonglong2 w2 = wp[q];
            asm("fma.rn.f32x2 %0, %1, %2, %0;" : "+l"(acc[2 * q]) : "l"(w2.x), "l"(h2));
            asm("fma.rn.f32x2 %0, %1, %2, %0;" : "+l"(acc[2 * q + 1]) : "l"(w2.y), "l"(h2));
        }
    }
    float* dst = out + ((size_t)b * TT + (TT - 1 - kd)) * FF;
#pragma unroll
    for (int q = 0; q < 16; ++q) {
        float2 a = *(float2*)&acc[2 * q];
        float2 bq = *(float2*)&acc[2 * q + 1];
        *(float4*)(dst + 4 * q) = make_float4(a.x, a.y, bq.x, bq.y);
    }
}

// ---------------- launch ----------------
extern "C" void kernel_launch(void* const* d_in, const int* in_sizes, int n_in,
                              void* d_out, int out_size) {
    (void)in_sizes; (void)n_in; (void)out_size;
    const float* ts       = (const float*)d_in[0];
    const float* w_ih_enc = (const float*)d_in[1];
    const float* w_hh_enc = (const float*)d_in[2];
    const float* b_ih_enc = (const float*)d_in[3];
    const float* b_hh_enc = (const float*)d_in[4];
    const float* w_ih_dec = (const float*)d_in[5];
    const float* w_hh_dec = (const float*)d_in[6];
    const float* b_ih_dec = (const float*)d_in[7];
    const float* b_hh_dec = (const float*)d_in[8];
    const float* w_out    = (const float*)d_in[9];
    const float* b_out    = (const float*)d_in[10];
    float* out = (float*)d_out;

    static bool attr_set = false;
    if (!attr_set) {
        cudaFuncSetAttribute(lstm_persistent,
                             cudaFuncAttributeMaxDynamicSharedMemorySize, SMEM_BYTES);
        attr_set = true;
    }
    reset_flags_kernel<<<1, 32>>>();
    lstm_persistent<<<NB, NT, SMEM_BYTES>>>(
        ts, w_ih_enc, w_hh_enc, b_ih_enc, b_hh_enc,
        w_ih_dec, w_hh_dec, b_ih_dec, b_hh_dec, w_out, b_out, out);
    y_final<<<TT, 128>>>(b_out, out);
}

// round 15
// speedup vs baseline: 1.6276x; 1.2254x over previous
#include <cuda_runtime.h>
#include <cuda_fp16.h>
#include <cstdint>

#define NB 128
#define NT 256          // 8 compute warps
#define BB 128
#define TT 1024
#define FF 64
#define HH 512

typedef unsigned long long ull;

// ---------------- device scratch ----------------
__device__ __align__(1024) unsigned char g_hh[2][8 * 16384];     // h fp16 chunk tiles
__device__ __align__(1024) unsigned char g_xh[(size_t)TT * 16384]; // x fp16 tiles
__device__ float g_hist[(size_t)TT * HH * BB];   // decoder-input h [kd][j][b]
__device__ float g_woutT[HH * FF];
__device__ unsigned int g_flag[8];
__device__ unsigned int g_count = 0, g_gen = 0;

// ---------------- smem byte offsets ----------------
#define OFF_WBE  0          // enc B frags: 9 ch * 2048 (fp16 hi only)
#define OFF_WBD  18432      // dec B frags: 8 ch * 2048
#define OFF_A    34816      // 3 stages * 16384
#define OFF_BE   83968      // 16 floats
#define OFF_BD   84032      // 16 floats
#define SMEM_BYTES 84096

static __device__ __forceinline__ uint32_t sw128(uint32_t o) {
    return o ^ ((o >> 3) & 0x70);
}
__device__ __forceinline__ float sigf(float x) {
    return __fdividef(1.0f, 1.0f + __expf(-x));
}
__device__ __forceinline__ float tanhfast(float x) {
    return 1.0f - __fdividef(2.0f, __expf(2.0f * x) + 1.0f);
}

__device__ __forceinline__ void grid_barrier_init() {
    __syncthreads();
    if (threadIdx.x == 0) {
        unsigned int cur0;
        asm volatile("ld.acquire.gpu.b32 %0, [%1];" : "=r"(cur0) : "l"(&g_gen) : "memory");
        unsigned int target = cur0 + 1u;
        __threadfence();
        unsigned int t = atomicAdd(&g_count, 1u);
        if (t == NB - 1u) {
            g_count = 0u;
            asm volatile("st.release.gpu.b32 [%0], %1;" :: "l"(&g_gen), "r"(target) : "memory");
        } else {
            unsigned int cur;
            do {
                __nanosleep(20);
                asm volatile("ld.acquire.gpu.b32 %0, [%1];" : "=r"(cur) : "l"(&g_gen) : "memory");
            } while ((int)(cur - target) < 0);
        }
    }
    __syncthreads();
}
__device__ __forceinline__ void wait_flag(int ch, unsigned int tgt) {
    unsigned int v;
    asm volatile("ld.acquire.gpu.b32 %0, [%1];" : "=r"(v) : "l"(&g_flag[ch]) : "memory");
    while ((int)(v - tgt) < 0) {
        __nanosleep(32);
        asm volatile("ld.acquire.gpu.b32 %0, [%1];" : "=r"(v) : "l"(&g_flag[ch]) : "memory");
    }
}

// stage one 16KB fp16 chunk: 4 cp.async.cg per thread
__device__ __forceinline__ void prefetch_chunk(uint32_t dst, const unsigned char* src, int tid) {
#pragma unroll
    for (int i = 0; i < 4; i++) {
        uint32_t off = (uint32_t)(tid + NT * i) * 16u;
        asm volatile("cp.async.cg.shared.global [%0], [%1], 16;"
                     :: "r"(dst + off), "l"(src + off) : "memory");
    }
    asm volatile("cp.async.commit_group;" ::: "memory");
}

__device__ __forceinline__ void ldmx4(uint32_t addr, uint32_t* a) {
    asm volatile("ldmatrix.sync.aligned.m8n8.x4.shared.b16 {%0,%1,%2,%3}, [%4];"
                 : "=r"(a[0]), "=r"(a[1]), "=r"(a[2]), "=r"(a[3]) : "r"(addr));
}
__device__ __forceinline__ void mma16816(float* d, const uint32_t* a, uint32_t b0, uint32_t b1) {
    asm volatile(
        "mma.sync.aligned.m16n8k16.row.col.f32.f16.f16.f32 "
        "{%0,%1,%2,%3}, {%4,%5,%6,%7}, {%8,%9}, {%0,%1,%2,%3};"
        : "+f"(d[0]), "+f"(d[1]), "+f"(d[2]), "+f"(d[3])
        : "r"(a[0]), "r"(a[1]), "r"(a[2]), "r"(a[3]), "r"(b0), "r"(b1));
}
__device__ __forceinline__ uint32_t pack_h2(float lo, float hi) {
    uint32_t r;
    asm("cvt.rn.f16x2.f32 %0, %1, %2;" : "=r"(r) : "f"(hi), "f"(lo));
    return r;
}

// consume one staged 16KB chunk: 4 ldmatrix + 8 LDS.64 + 8 HMMA
__device__ __forceinline__ void consume_chunk(uint32_t sa, uint32_t wb,
                                              uint32_t abase, int lane,
                                              float* D0, float* D1) {
#pragma unroll
    for (int ks = 0; ks < 4; ++ks) {
        uint32_t ao = sw128(abase + (uint32_t)ks * 32u);
        uint32_t a[4];
        ldmx4(sa + ao, a);
#pragma unroll
        for (int nt = 0; nt < 2; ++nt) {
            uint32_t fb = wb + (uint32_t)(ks * 2 + nt) * 256u + (uint32_t)lane * 8u;
            uint32_t bh0, bh1;
            asm("ld.shared.v2.b32 {%0,%1}, [%2];" : "=r"(bh0), "=r"(bh1) : "r"(fb));
            float* D = nt ? D1 : D0;
            mma16816(D, a, bh0, bh1);
        }
    }
}

__global__ void reset_flags_kernel() {
    if (threadIdx.x < 8) g_flag[threadIdx.x] = 16u;   // h_0 ready baseline
}

__global__ void __launch_bounds__(NT, 1) lstm_persistent(
    const float* __restrict__ ts,
    const float* __restrict__ w_ih_enc, const float* __restrict__ w_hh_enc,
    const float* __restrict__ b_ih_enc, const float* __restrict__ b_hh_enc,
    const float* __restrict__ w_ih_dec, const float* __restrict__ w_hh_dec,
    const float* __restrict__ b_ih_dec, const float* __restrict__ b_hh_dec,
    const float* __restrict__ w_out, const float* __restrict__ b_out,
    float* __restrict__ out)
{
    extern __shared__ unsigned char smem[];
    const int tid = threadIdx.x;
    const int cid = blockIdx.x;
    const int jb = cid * 4;
    const int gidx = cid >> 4;
    const uint32_t sb = (uint32_t)__cvta_generic_to_shared(smem);

    // ======== INIT: encoder B fragments, fp16 (single stream) ========
    for (int e = tid; e < 9 * 4 * 2 * 32; e += NT) {
        int lane = e & 31, rem = e >> 5;
        int nt = rem & 1, ks = (rem >> 1) & 3, ch = rem >> 3;
        int gid = lane >> 2, tig = lane & 3;
        int n = nt * 8 + gid, jl = n >> 2, q = n & 3;
        int row = q * HH + jb + jl;
        float v[4];
#pragma unroll
        for (int d = 0; d < 4; ++d) {
            int kin = ks * 16 + 2 * tig + ((d & 2) ? 8 : 0) + (d & 1);
            v[d] = (ch < 8) ? w_hh_enc[(size_t)row * HH + ch * 64 + kin]
                            : w_ih_enc[(size_t)row * FF + kin];
        }
        uint32_t base = (uint32_t)(ch * 8 + ks * 2 + nt) * 256u + (uint32_t)lane * 8u;
        uint32_t* ph = (uint32_t*)(smem + OFF_WBE + base);
        ph[0] = pack_h2(v[0], v[1]); ph[1] = pack_h2(v[2], v[3]);
    }
    // ======== INIT: decoder fused B fragments (W_eff = w_hh + w_ih @ w_out) ========
    for (int e = tid; e < 8 * 4 * 2 * 32; e += NT) {
        int lane = e & 31, rem = e >> 5;
        int nt = rem & 1, ks = (rem >> 1) & 3, ch = rem >> 3;
        int gid = lane >> 2, tig = lane & 3;
        int n = nt * 8 + gid, jl = n >> 2, q = n & 3;
        int row = q * HH + jb + jl;
        const float* wr = w_ih_dec + (size_t)row * FF;
        float v[4];
#pragma unroll
        for (int d = 0; d < 4; ++d) {
            int k = ch * 64 + ks * 16 + 2 * tig + ((d & 2) ? 8 : 0) + (d & 1);
            float acc = w_hh_dec[(size_t)row * HH + k];
#pragma unroll 8
            for (int f = 0; f < FF; ++f) acc += wr[f] * w_out[(size_t)f * HH + k];
            v[d] = acc;
        }
        uint32_t base = (uint32_t)(ch * 8 + ks * 2 + nt) * 256u + (uint32_t)lane * 8u;
        uint32_t* ph = (uint32_t*)(smem + OFF_WBD + base);
        ph[0] = pack_h2(v[0], v[1]); ph[1] = pack_h2(v[2], v[3]);
    }
    // biases [jl][q]
    if (tid < 16) {
        int jl = tid >> 2, q = tid & 3;
        int row = q * HH + jb + jl;
        ((float*)(smem + OFF_BE))[jl * 4 + q] = b_ih_enc[row] + b_hh_enc[row];
        float v = b_ih_dec[row] + b_hh_dec[row];
        const float* wr = w_ih_dec + (size_t)row * FF;
#pragma unroll 8
        for (int f = 0; f < FF; ++f) v += wr[f] * b_out[f];
        ((float*)(smem + OFF_BD))[jl * 4 + q] = v;
    }
    // x tiles: [t][b*128B] fp16, swizzled; 8 t per CTA
    for (int tt = 0; tt < TT / NB; ++tt) {
        int t = cid * (TT / NB) + tt;
        for (int idx = tid; idx < BB * 16; idx += NT) {
            int b = idx >> 4, f4 = (idx & 15) * 4;
            float v0 = ts[((size_t)b * TT + t) * FF + f4];
            float v1 = ts[((size_t)b * TT + t) * FF + f4 + 1];
            float v2 = ts[((size_t)b * TT + t) * FF + f4 + 2];
            float v3 = ts[((size_t)b * TT + t) * FF + f4 + 3];
            uint32_t o = sw128((uint32_t)(b * 128 + f4 * 2));
            *(uint2*)(g_xh + (size_t)t * 16384 + o) =
                make_uint2(pack_h2(v0, v1), pack_h2(v2, v3));
        }
    }
    // zero own h_0 slice (4 cols x 128 b)
    if (tid < 128) {
        uint32_t o = sw128((uint32_t)(tid * 128 + (cid & 15) * 8));
        *(uint2*)(g_hh[0] + (size_t)gidx * 16384 + o) = make_uint2(0, 0);
    }
    if (cid == 0) {
        for (int idx = tid; idx < HH * FF; idx += NT) {
            int j = idx >> 6, f = idx & 63;
            g_woutT[j * FF + f] = w_out[(size_t)f * HH + j];
        }
    }
    grid_barrier_init();

    // ======== persistent recurrence ========
    const int w = tid >> 5, lane = tid & 31;
    const int gid = lane >> 2, tig = lane & 3;
    const uint32_t abase = (uint32_t)(((w << 4) + (lane & 15)) * 128 + ((lane >> 4) & 1) * 16);

    float c0s = 0.0f, c8s = 0.0f;

    for (int s = 0; s < 2 * TT; ++s) {
        const bool enc = (s < TT);
        const int nc = enc ? 9 : 8;
        if (s == TT) { c0s = 0.0f; c8s = 0.0f; }
        const unsigned int tgt = 16u * (unsigned)(s + 1);

        if (tid < 8) wait_flag(tid, tgt);    // parallel upfront wait
        __syncthreads();

        const unsigned char* hh = g_hh[s & 1];
#define SRC(i) (enc ? ((i) == 0 ? g_xh + (size_t)s * 16384 : hh + (size_t)((i) - 1) * 16384) \
                    : hh + (size_t)(i) * 16384)

        prefetch_chunk(sb + OFF_A, SRC(0), tid);
        prefetch_chunk(sb + OFF_A + 16384u, SRC(1), tid);

        float D0[4] = {0, 0, 0, 0}, D1[4] = {0, 0, 0, 0};

        for (int i = 0; i < nc; ++i) {
            if (i + 1 < nc) {
                asm volatile("cp.async.wait_group 1;" ::: "memory");
            } else {
                asm volatile("cp.async.wait_group 0;" ::: "memory");
            }
            __syncthreads();   // chunk i landed; stage (i+2)%3 free
            if (i + 2 < nc) {
                prefetch_chunk(sb + OFF_A + (uint32_t)((i + 2) % 3) * 16384u, SRC(i + 2), tid);
            }
            int ch = enc ? (i == 0 ? 8 : i - 1) : i;
            uint32_t wb = sb + (enc ? OFF_WBE : OFF_WBD) + (uint32_t)ch * 2048u;
            consume_chunk(sb + OFF_A + (uint32_t)(i % 3) * 16384u, wb, abase, lane, D0, D1);
        }
#undef SRC

        // ---- epilogue: gate pairing via shfl, cell update ----
        bool ev = ((tig & 1) == 0);
        float s0 = ev ? D1[0] : D0[0];
        float s1 = ev ? D1[1] : D0[1];
        float s2 = ev ? D1[2] : D0[2];
        float s3 = ev ? D1[3] : D0[3];
        float r0 = __shfl_xor_sync(0xffffffffu, s0, 1);
        float r1 = __shfl_xor_sync(0xffffffffu, s1, 1);
        float r2 = __shfl_xor_sync(0xffffffffu, s2, 1);
        float r3 = __shfl_xor_sync(0xffffffffu, s3, 1);
        float gi0, gf0, gi8, gf8, gg0, go0, gg8, go8;
        int jl;
        if (ev) {
            gi0 = D0[0]; gf0 = D0[1]; gi8 = D0[2]; gf8 = D0[3];
            gg0 = r0; go0 = r1; gg8 = r2; go8 = r3;
            jl = tig >> 1;
        } else {
            gi0 = r0; gf0 = r1; gi8 = r2; gf8 = r3;
            gg0 = D1[0]; go0 = D1[1]; gg8 = D1[2]; go8 = D1[3];
            jl = (tig >> 1) + 2;
        }
        float4 bi = ((const float4*)(smem + (enc ? OFF_BE : OFF_BD)))[jl];
        float iv0 = sigf(gi0 + bi.x), fv0 = sigf(gf0 + bi.y);
        float gv0 = tanhfast(gg0 + bi.z), ov0 = sigf(go0 + bi.w);
        float iv8 = sigf(gi8 + bi.x), fv8 = sigf(gf8 + bi.y);
        float gv8 = tanhfast(gg8 + bi.z), ov8 = sigf(go8 + bi.w);
        c0s = fv0 * c0s + iv0 * gv0;
        c8s = fv8 * c8s + iv8 * gv8;
        float h0 = ov0 * tanhfast(c0s);
        float h8 = ov8 * tanhfast(c8s);

        int b0r = (w << 4) + gid;
        uint32_t colb = (uint32_t)((((cid & 15) << 2) + jl) << 1);
        uint32_t o0 = sw128((uint32_t)(b0r * 128) + colb);
        uint32_t o8 = sw128((uint32_t)((b0r + 8) * 128) + colb);
        int nb2 = (s + 1) & 1;
        size_t tb = (size_t)gidx * 16384;
        *(__half*)(g_hh[nb2] + tb + o0) = __float2half_rn(h0);
        *(__half*)(g_hh[nb2] + tb + o8) = __float2half_rn(h8);
        if (s >= TT - 1 && s < 2 * TT - 1) {
            int kd = s - (TT - 1);
            float* hb = g_hist + ((size_t)kd * HH + (jb + jl)) * BB;
            hb[b0r] = h0;
            hb[b0r + 8] = h8;
        }
        __syncthreads();
        if (tid == 0) {
            __threadfence();
            atomicAdd(&g_flag[gidx], 1u);
        }
    }
}

// ============ final y pass: out[b][T-1-kd][:] = hist[kd]·w_outT + b_out ============
__global__ void __launch_bounds__(128) y_final(const float* __restrict__ b_out,
                                               float* __restrict__ out) {
    const int kd = blockIdx.x;
    const int b = threadIdx.x;
    ull acc[32];
#pragma unroll
    for (int q = 0; q < 32; ++q) {
        float2 bo = *(const float2*)(b_out + 2 * q);
        asm("mov.b64 %0, {%1, %2};" : "=l"(acc[q]) : "f"(bo.x), "f"(bo.y));
    }
    const float* hp = g_hist + (size_t)kd * HH * BB + b;
#pragma unroll 4
    for (int j = 0; j < HH; ++j) {
        float hv = hp[(size_t)j * BB];
        ull h2;
        asm("mov.b64 %0, {%1, %2};" : "=l"(h2) : "f"(hv), "f"(hv));
        const ulonglong2* wp = (const ulonglong2*)(g_woutT + j * FF);
#pragma unroll
        for (int q = 0; q < 16; ++q) {
            ulonglong2 w2 = wp[q];
            asm("fma.rn.f32x2 %0, %1, %2, %0;" : "+l"(acc[2 * q]) : "l"(w2.x), "l"(h2));
            asm("fma.rn.f32x2 %0, %1, %2, %0;" : "+l"(acc[2 * q + 1]) : "l"(w2.y), "l"(h2));
        }
    }
    float* dst = out + ((size_t)b * TT + (TT - 1 - kd)) * FF;
#pragma unroll
    for (int q = 0; q < 16; ++q) {
        float2 a = *(float2*)&acc[2 * q];
        float2 bq = *(float2*)&acc[2 * q + 1];
        *(float4*)(dst + 4 * q) = make_float4(a.x, a.y, bq.x, bq.y);
    }
}

// ---------------- launch ----------------
extern "C" void kernel_launch(void* const* d_in, const int* in_sizes, int n_in,
                              void* d_out, int out_size) {
    (void)in_sizes; (void)n_in; (void)out_size;
    const float* ts       = (const float*)d_in[0];
    const float* w_ih_enc = (const float*)d_in[1];
    const float* w_hh_enc = (const float*)d_in[2];
    const float* b_ih_enc = (const float*)d_in[3];
    const float* b_hh_enc = (const float*)d_in[4];
    const float* w_ih_dec = (const float*)d_in[5];
    const float* w_hh_dec = (const float*)d_in[6];
    const float* b_ih_dec = (const float*)d_in[7];
    const float* b_hh_dec = (const float*)d_in[8];
    const float* w_out    = (const float*)d_in[9];
    const float* b_out    = (const float*)d_in[10];
    float* out = (float*)d_out;

    static bool attr_set = false;
    if (!attr_set) {
        cudaFuncSetAttribute(lstm_persistent,
                             cudaFuncAttributeMaxDynamicSharedMemorySize, SMEM_BYTES);
        attr_set = true;
    }
    reset_flags_kernel<<<1, 32>>>();
    lstm_persistent<<<NB, NT, SMEM_BYTES>>>(
        ts, w_ih_enc, w_hh_enc, b_ih_enc, b_hh_enc,
        w_ih_dec, w_hh_dec, b_ih_dec, b_hh_dec, w_out, b_out, out);
    y_final<<<TT, 128>>>(b_out, out);
}

// round 16
// speedup vs baseline: 1.7864x; 1.0975x over previous
#include <cuda_runtime.h>
#include <cuda_fp16.h>
#include <cstdint>

#define NB 128
#define NT 256          // 8 compute warps
#define BB 128
#define TT 1024
#define FF 64
#define HH 512

typedef unsigned long long ull;

// ---------------- device scratch ----------------
__device__ __align__(1024) unsigned char g_hh[2][8 * 16384];     // h fp16 chunk tiles
__device__ __align__(1024) unsigned char g_xh[(size_t)TT * 16384]; // x fp16 tiles
__device__ float g_hist[(size_t)TT * HH * BB];   // decoder-input h [kd][j][b]
__device__ float g_woutT[HH * FF];
__device__ unsigned int g_flag[8];
__device__ unsigned int g_count = 0, g_gen = 0;

// ---------------- smem byte offsets ----------------
#define OFF_WBE  0          // enc B frags: 9 ch * 2048 (fp16)
#define OFF_WBD  18432      // dec B frags: 8 ch * 2048
#define OFF_A    34816      // 3 stages * 16384
#define OFF_BE   83968      // 16 floats
#define OFF_BD   84032      // 16 floats
#define SMEM_BYTES 84096

static __device__ __forceinline__ uint32_t sw128(uint32_t o) {
    return o ^ ((o >> 3) & 0x70);
}
__device__ __forceinline__ float sigf(float x) {
    return __fdividef(1.0f, 1.0f + __expf(-x));
}
__device__ __forceinline__ float tanhfast(float x) {
    return 1.0f - __fdividef(2.0f, __expf(2.0f * x) + 1.0f);
}

__device__ __forceinline__ void grid_barrier_init() {
    __syncthreads();
    if (threadIdx.x == 0) {
        unsigned int cur0;
        asm volatile("ld.acquire.gpu.b32 %0, [%1];" : "=r"(cur0) : "l"(&g_gen) : "memory");
        unsigned int target = cur0 + 1u;
        __threadfence();
        unsigned int t = atomicAdd(&g_count, 1u);
        if (t == NB - 1u) {
            g_count = 0u;
            asm volatile("st.release.gpu.b32 [%0], %1;" :: "l"(&g_gen), "r"(target) : "memory");
        } else {
            unsigned int cur;
            do {
                __nanosleep(20);
                asm volatile("ld.acquire.gpu.b32 %0, [%1];" : "=r"(cur) : "l"(&g_gen) : "memory");
            } while ((int)(cur - target) < 0);
        }
    }
    __syncthreads();
}
__device__ __forceinline__ void wait_flag(int ch, unsigned int tgt) {
    unsigned int v;
    asm volatile("ld.acquire.gpu.b32 %0, [%1];" : "=r"(v) : "l"(&g_flag[ch]) : "memory");
    while ((int)(v - tgt) < 0) {
        __nanosleep(32);
        asm volatile("ld.acquire.gpu.b32 %0, [%1];" : "=r"(v) : "l"(&g_flag[ch]) : "memory");
    }
}

// warp-private prefetch: warp w's 2KB row-slice (rows 16w..16w+15) of one chunk
__device__ __forceinline__ void prefetch_slice(uint32_t dst_stage, const unsigned char* src,
                                               uint32_t wslice, int lane) {
#pragma unroll
    for (int i = 0; i < 4; i++) {
        uint32_t off = wslice + (uint32_t)lane * 16u + (uint32_t)i * 512u;
        asm volatile("cp.async.cg.shared.global [%0], [%1], 16;"
                     :: "r"(dst_stage + off), "l"(src + off) : "memory");
    }
    asm volatile("cp.async.commit_group;" ::: "memory");
}

__device__ __forceinline__ void ldmx4(uint32_t addr, uint32_t* a) {
    asm volatile("ldmatrix.sync.aligned.m8n8.x4.shared.b16 {%0,%1,%2,%3}, [%4];"
                 : "=r"(a[0]), "=r"(a[1]), "=r"(a[2]), "=r"(a[3]) : "r"(addr));
}
__device__ __forceinline__ void mma16816(float* d, const uint32_t* a, uint32_t b0, uint32_t b1) {
    asm volatile(
        "mma.sync.aligned.m16n8k16.row.col.f32.f16.f16.f32 "
        "{%0,%1,%2,%3}, {%4,%5,%6,%7}, {%8,%9}, {%0,%1,%2,%3};"
        : "+f"(d[0]), "+f"(d[1]), "+f"(d[2]), "+f"(d[3])
        : "r"(a[0]), "r"(a[1]), "r"(a[2]), "r"(a[3]), "r"(b0), "r"(b1));
}
__device__ __forceinline__ uint32_t pack_h2(float lo, float hi) {
    uint32_t r;
    asm("cvt.rn.f16x2.f32 %0, %1, %2;" : "=r"(r) : "f"(hi), "f"(lo));
    return r;
}

// consume one staged chunk: 4 ldmatrix + 8 LDS.64 + 8 HMMA
__device__ __forceinline__ void consume_chunk(uint32_t sa, uint32_t wb,
                                              uint32_t abase, int lane,
                                              float* D0, float* D1) {
#pragma unroll
    for (int ks = 0; ks < 4; ++ks) {
        uint32_t ao = sw128(abase + (uint32_t)ks * 32u);
        uint32_t a[4];
        ldmx4(sa + ao, a);
#pragma unroll
        for (int nt = 0; nt < 2; ++nt) {
            uint32_t fb = wb + (uint32_t)(ks * 2 + nt) * 256u + (uint32_t)lane * 8u;
            uint32_t bh0, bh1;
            asm("ld.shared.v2.b32 {%0,%1}, [%2];" : "=r"(bh0), "=r"(bh1) : "r"(fb));
            float* D = nt ? D1 : D0;
            mma16816(D, a, bh0, bh1);
        }
    }
}

__global__ void reset_flags_kernel() {
    if (threadIdx.x < 8) g_flag[threadIdx.x] = 16u;   // h_0 ready baseline
}

__global__ void __launch_bounds__(NT, 1) lstm_persistent(
    const float* __restrict__ ts,
    const float* __restrict__ w_ih_enc, const float* __restrict__ w_hh_enc,
    const float* __restrict__ b_ih_enc, const float* __restrict__ b_hh_enc,
    const float* __restrict__ w_ih_dec, const float* __restrict__ w_hh_dec,
    const float* __restrict__ b_ih_dec, const float* __restrict__ b_hh_dec,
    const float* __restrict__ w_out, const float* __restrict__ b_out,
    float* __restrict__ out)
{
    extern __shared__ unsigned char smem[];
    const int tid = threadIdx.x;
    const int cid = blockIdx.x;
    const int jb = cid * 4;
    const int gidx = cid >> 4;
    const uint32_t sb = (uint32_t)__cvta_generic_to_shared(smem);

    // ======== INIT: encoder B fragments, fp16 ========
    for (int e = tid; e < 9 * 4 * 2 * 32; e += NT) {
        int lane = e & 31, rem = e >> 5;
        int nt = rem & 1, ks = (rem >> 1) & 3, ch = rem >> 3;
        int gid = lane >> 2, tig = lane & 3;
        int n = nt * 8 + gid, jl = n >> 2, q = n & 3;
        int row = q * HH + jb + jl;
        float v[4];
#pragma unroll
        for (int d = 0; d < 4; ++d) {
            int kin = ks * 16 + 2 * tig + ((d & 2) ? 8 : 0) + (d & 1);
            v[d] = (ch < 8) ? w_hh_enc[(size_t)row * HH + ch * 64 + kin]
                            : w_ih_enc[(size_t)row * FF + kin];
        }
        uint32_t base = (uint32_t)(ch * 8 + ks * 2 + nt) * 256u + (uint32_t)lane * 8u;
        uint32_t* ph = (uint32_t*)(smem + OFF_WBE + base);
        ph[0] = pack_h2(v[0], v[1]); ph[1] = pack_h2(v[2], v[3]);
    }
    // ======== INIT: decoder fused B fragments (W_eff = w_hh + w_ih @ w_out) ========
    for (int e = tid; e < 8 * 4 * 2 * 32; e += NT) {
        int lane = e & 31, rem = e >> 5;
        int nt = rem & 1, ks = (rem >> 1) & 3, ch = rem >> 3;
        int gid = lane >> 2, tig = lane & 3;
        int n = nt * 8 + gid, jl = n >> 2, q = n & 3;
        int row = q * HH + jb + jl;
        const float* wr = w_ih_dec + (size_t)row * FF;
        float v[4];
#pragma unroll
        for (int d = 0; d < 4; ++d) {
            int k = ch * 64 + ks * 16 + 2 * tig + ((d & 2) ? 8 : 0) + (d & 1);
            float acc = w_hh_dec[(size_t)row * HH + k];
#pragma unroll 8
            for (int f = 0; f < FF; ++f) acc += wr[f] * w_out[(size_t)f * HH + k];
            v[d] = acc;
        }
        uint32_t base = (uint32_t)(ch * 8 + ks * 2 + nt) * 256u + (uint32_t)lane * 8u;
        uint32_t* ph = (uint32_t*)(smem + OFF_WBD + base);
        ph[0] = pack_h2(v[0], v[1]); ph[1] = pack_h2(v[2], v[3]);
    }
    // biases [jl][q]
    if (tid < 16) {
        int jl = tid >> 2, q = tid & 3;
        int row = q * HH + jb + jl;
        ((float*)(smem + OFF_BE))[jl * 4 + q] = b_ih_enc[row] + b_hh_enc[row];
        float v = b_ih_dec[row] + b_hh_dec[row];
        const float* wr = w_ih_dec + (size_t)row * FF;
#pragma unroll 8
        for (int f = 0; f < FF; ++f) v += wr[f] * b_out[f];
        ((float*)(smem + OFF_BD))[jl * 4 + q] = v;
    }
    // x tiles: [t][b*128B] fp16, swizzled; 8 t per CTA
    for (int tt = 0; tt < TT / NB; ++tt) {
        int t = cid * (TT / NB) + tt;
        for (int idx = tid; idx < BB * 16; idx += NT) {
            int b = idx >> 4, f4 = (idx & 15) * 4;
            float v0 = ts[((size_t)b * TT + t) * FF + f4];
            float v1 = ts[((size_t)b * TT + t) * FF + f4 + 1];
            float v2 = ts[((size_t)b * TT + t) * FF + f4 + 2];
            float v3 = ts[((size_t)b * TT + t) * FF + f4 + 3];
            uint32_t o = sw128((uint32_t)(b * 128 + f4 * 2));
            *(uint2*)(g_xh + (size_t)t * 16384 + o) =
                make_uint2(pack_h2(v0, v1), pack_h2(v2, v3));
        }
    }
    // zero own h_0 slice (4 cols x 128 b)
    if (tid < 128) {
        uint32_t o = sw128((uint32_t)(tid * 128 + (cid & 15) * 8));
        *(uint2*)(g_hh[0] + (size_t)gidx * 16384 + o) = make_uint2(0, 0);
    }
    if (cid == 0) {
        for (int idx = tid; idx < HH * FF; idx += NT) {
            int j = idx >> 6, f = idx & 63;
            g_woutT[j * FF + f] = w_out[(size_t)f * HH + j];
        }
    }
    grid_barrier_init();

    // ======== persistent recurrence: warp-autonomous chunk pipeline ========
    const int w = tid >> 5, lane = tid & 31;
    const int gid = lane >> 2, tig = lane & 3;
    const uint32_t abase = (uint32_t)(((w << 4) + (lane & 15)) * 128 + ((lane >> 4) & 1) * 16);
    const uint32_t wslice = (uint32_t)w * 2048u;   // warp's row-slice byte offset in tile

    float c0s = 0.0f, c8s = 0.0f;

    for (int s = 0; s < 2 * TT; ++s) {
        const bool enc = (s < TT);
        const int nc = enc ? 9 : 8;
        if (s == TT) { c0s = 0.0f; c8s = 0.0f; }
        const unsigned int tgt = 16u * (unsigned)(s + 1);

        // per-warp flag wait (no CTA barrier): lanes 0..7 poll the 8 flags
        if (lane < 8) wait_flag(lane, tgt);
        __syncwarp();

        const unsigned char* hh = g_hh[s & 1];
#define SRC(i) (enc ? ((i) == 0 ? g_xh + (size_t)s * 16384 : hh + (size_t)((i) - 1) * 16384) \
                    : hh + (size_t)(i) * 16384)

        prefetch_slice(sb + OFF_A, SRC(0), wslice, lane);
        prefetch_slice(sb + OFF_A + 16384u, SRC(1), wslice, lane);

        float D0[4] = {0, 0, 0, 0}, D1[4] = {0, 0, 0, 0};

        for (int i = 0; i < nc; ++i) {
            if (i + 1 < nc) {
                asm volatile("cp.async.wait_group 1;" ::: "memory");
            } else {
                asm volatile("cp.async.wait_group 0;" ::: "memory");
            }
            if (i + 2 < nc) {
                prefetch_slice(sb + OFF_A + (uint32_t)((i + 2) % 3) * 16384u,
                               SRC(i + 2), wslice, lane);
            }
            int ch = enc ? (i == 0 ? 8 : i - 1) : i;
            uint32_t wb = sb + (enc ? OFF_WBE : OFF_WBD) + (uint32_t)ch * 2048u;
            consume_chunk(sb + OFF_A + (uint32_t)(i % 3) * 16384u, wb, abase, lane, D0, D1);
        }
#undef SRC

        // ---- epilogue: gate pairing via shfl, cell update ----
        bool ev = ((tig & 1) == 0);
        float s0 = ev ? D1[0] : D0[0];
        float s1 = ev ? D1[1] : D0[1];
        float s2 = ev ? D1[2] : D0[2];
        float s3 = ev ? D1[3] : D0[3];
        float r0 = __shfl_xor_sync(0xffffffffu, s0, 1);
        float r1 = __shfl_xor_sync(0xffffffffu, s1, 1);
        float r2 = __shfl_xor_sync(0xffffffffu, s2, 1);
        float r3 = __shfl_xor_sync(0xffffffffu, s3, 1);
        float gi0, gf0, gi8, gf8, gg0, go0, gg8, go8;
        int jl;
        if (ev) {
            gi0 = D0[0]; gf0 = D0[1]; gi8 = D0[2]; gf8 = D0[3];
            gg0 = r0; go0 = r1; gg8 = r2; go8 = r3;
            jl = tig >> 1;
        } else {
            gi0 = r0; gf0 = r1; gi8 = r2; gf8 = r3;
            gg0 = D1[0]; go0 = D1[1]; gg8 = D1[2]; go8 = D1[3];
            jl = (tig >> 1) + 2;
        }
        float4 bi = ((const float4*)(smem + (enc ? OFF_BE : OFF_BD)))[jl];
        float iv0 = sigf(gi0 + bi.x), fv0 = sigf(gf0 + bi.y);
        float gv0 = tanhfast(gg0 + bi.z), ov0 = sigf(go0 + bi.w);
        float iv8 = sigf(gi8 + bi.x), fv8 = sigf(gf8 + bi.y);
        float gv8 = tanhfast(gg8 + bi.z), ov8 = sigf(go8 + bi.w);
        c0s = fv0 * c0s + iv0 * gv0;
        c8s = fv8 * c8s + iv8 * gv8;
        float h0 = ov0 * tanhfast(c0s);
        float h8 = ov8 * tanhfast(c8s);

        int b0r = (w << 4) + gid;
        uint32_t colb = (uint32_t)((((cid & 15) << 2) + jl) << 1);
        uint32_t o0 = sw128((uint32_t)(b0r * 128) + colb);
        uint32_t o8 = sw128((uint32_t)((b0r + 8) * 128) + colb);
        int nb2 = (s + 1) & 1;
        size_t tb = (size_t)gidx * 16384;
        *(__half*)(g_hh[nb2] + tb + o0) = __float2half_rn(h0);
        *(__half*)(g_hh[nb2] + tb + o8) = __float2half_rn(h8);
        if (s >= TT - 1 && s < 2 * TT - 1) {
            int kd = s - (TT - 1);
            float* hb = g_hist + ((size_t)kd * HH + (jb + jl)) * BB;
            hb[b0r] = h0;
            hb[b0r + 8] = h8;
        }
        __syncthreads();   // all warps' h-stores done before release
        if (tid == 0) {
            __threadfence();
            atomicAdd(&g_flag[gidx], 1u);
        }
    }
}

// ============ final y pass: out[b][T-1-kd][:] = hist[kd]·w_outT + b_out ============
__global__ void __launch_bounds__(128) y_final(const float* __restrict__ b_out,
                                               float* __restrict__ out) {
    const int kd = blockIdx.x;
    const int b = threadIdx.x;
    ull acc[32];
#pragma unroll
    for (int q = 0; q < 32; ++q) {
        float2 bo = *(const float2*)(b_out + 2 * q);
        asm("mov.b64 %0, {%1, %2};" : "=l"(acc[q]) : "f"(bo.x), "f"(bo.y));
    }
    const float* hp = g_hist + (size_t)kd * HH * BB + b;
#pragma unroll 4
    for (int j = 0; j < HH; ++j) {
        float hv = hp[(size_t)j * BB];
        ull h2;
        asm("mov.b64 %0, {%1, %2};" : "=l"(h2) : "f"(hv), "f"(hv));
        const ulonglong2* wp = (const ulonglong2*)(g_woutT + j * FF);
#pragma unroll
        for (int q = 0; q < 16; ++q) {
            ulonglong2 w2 = wp[q];
            asm("fma.rn.f32x2 %0, %1, %2, %0;" : "+l"(acc[2 * q]) : "l"(w2.x), "l"(h2));
            asm("fma.rn.f32x2 %0, %1, %2, %0;" : "+l"(acc[2 * q + 1]) : "l"(w2.y), "l"(h2));
        }
    }
    float* dst = out + ((size_t)b * TT + (TT - 1 - kd)) * FF;
#pragma unroll
    for (int q = 0; q < 16; ++q) {
        float2 a = *(float2*)&acc[2 * q];
        float2 bq = *(float2*)&acc[2 * q + 1];
        *(float4*)(dst + 4 * q) = make_float4(a.x, a.y, bq.x, bq.y);
    }
}

// ---------------- launch ----------------
extern "C" void kernel_launch(void* const* d_in, const int* in_sizes, int n_in,
                              void* d_out, int out_size) {
    (void)in_sizes; (void)n_in; (void)out_size;
    const float* ts       = (const float*)d_in[0];
    const float* w_ih_enc = (const float*)d_in[1];
    const float* w_hh_enc = (const float*)d_in[2];
    const float* b_ih_enc = (const float*)d_in[3];
    const float* b_hh_enc = (const float*)d_in[4];
    const float* w_ih_dec = (const float*)d_in[5];
    const float* w_hh_dec = (const float*)d_in[6];
    const float* b_ih_dec = (const float*)d_in[7];
    const float* b_hh_dec = (const float*)d_in[8];
    const float* w_out    = (const float*)d_in[9];
    const float* b_out    = (const float*)d_in[10];
    float* out = (float*)d_out;

    static bool attr_set = false;
    if (!attr_set) {
        cudaFuncSetAttribute(lstm_persistent,
                             cudaFuncAttributeMaxDynamicSharedMemorySize, SMEM_BYTES);
        attr_set = true;
    }
    reset_flags_kernel<<<1, 32>>>();
    lstm_persistent<<<NB, NT, SMEM_BYTES>>>(
        ts, w_ih_enc, w_hh_enc, b_ih_enc, b_hh_enc,
        w_ih_dec, w_hh_dec, b_ih_dec, b_hh_dec, w_out, b_out, out);
    y_final<<<TT, 128>>>(b_out, out);
}